// round 5
// baseline (speedup 1.0000x reference)
#include <cuda_runtime.h>

// QLSTM on GB300. One CTA/batch element, T=64 recurrence in-kernel.
// 4 circuits/CTA, 2 warps per circuit, 16 amps/thread.
// Per step/circuit (2 smem round trips only):
//   FusedPA+P4: product state (encoding + L1 rotations + L1 CNOT ring folded
//     via ring^-1 index algebra) built in registers, L2 wires 0-3 applied,
//     write rot4 -> bufY
//   P5: read bufY, L2 wires 4-7, write rot4 -> bufX
//   P6: read bufX, L2 wires 8-9, probs + Walsh expectations (L2 ring folded
//     into parity masks)
// 3 named 64-thread barriers + 1 __syncthreads per step.

#define TT 64
#define BB 256
#define DD 32
#define HH 10
#define NTH 256

typedef unsigned long long u64;

struct Smem {
    u64    sv0[4][1024];
    u64    sv1[4][1024];
    u64    sUc[HH][6];           // layer-2 packed su2 consts
    float4 sU0[HH];              // layer-1 (ax,ay,bx,by)
    u64    venc[4][HH][2];       // per-wire 2-vectors (enc + L1 rot)
    u64    Ttab[4][16];          // wires 0-3 product table
    float  sW[4][HH][42];
    float  sBias[4][HH];
    float  qpart[2][4][2][9];    // [parity][circuit][warp][slot]
    float  comb_x[2][DD];
};

__device__ __forceinline__ u64 f2fma(u64 a, u64 b, u64 c) {
    u64 d;
    asm("fma.rn.f32x2 %0, %1, %2, %3;" : "=l"(d) : "l"(a), "l"(b), "l"(c));
    return d;
}
__device__ __forceinline__ u64 f2mul(u64 a, u64 b) {
    u64 d;
    asm("mul.rn.f32x2 %0, %1, %2;" : "=l"(d) : "l"(a), "l"(b));
    return d;
}
__device__ __forceinline__ u64 dswp(u64 a) {
    u64 r;
    asm("{\n\t.reg .b32 l, h;\n\tmov.b64 {l, h}, %1;\n\tmov.b64 %0, {h, l};\n\t}"
        : "=l"(r) : "l"(a));
    return r;
}
__device__ __forceinline__ u64 pk(float lo, float hi) {
    return (u64)__float_as_uint(lo) | ((u64)__float_as_uint(hi) << 32);
}
__device__ __forceinline__ float ulo(u64 v) { return __uint_as_float((unsigned)v); }
__device__ __forceinline__ float uhi(u64 v) { return __uint_as_float((unsigned)(v >> 32)); }

// xlow4 linear part of ring^-1 as function of j (compile-time)
__host__ __device__ constexpr int XLJ(int j) {
    return ((j & 1) ? 0x3 : 0) ^ ((j & 2) ? 0x6 : 0) ^
           ((j & 4) ? 0xC : 0) ^ ((j & 8) ? 0x8 : 0);
}

__device__ __forceinline__ void cbar(int c) {
    asm volatile("bar.sync %0, 64;" :: "r"(c + 1) : "memory");
}

// packed su2 on register bit B across the 16-amp tile
template<int B>
__device__ __forceinline__ void apply_bit16(u64 a[16], const u64* __restrict__ C) {
    u64 c0 = C[0], c1 = C[1], c2 = C[2], c3 = C[3], c4 = C[4], c5 = C[5];
#pragma unroll
    for (int m = 0; m < 16; ++m) {
        if (m & (1 << B)) continue;
        const int m1 = m | (1 << B);
        u64 s0 = dswp(a[m]), s1 = dswp(a[m1]);
        u64 n0 = f2mul(c3, s1);
        n0 = f2fma(c2, a[m1], n0);
        n0 = f2fma(c1, s0, n0);
        n0 = f2fma(c0, a[m], n0);
        u64 n1 = f2mul(c5, s1);
        n1 = f2fma(c0, a[m1], n1);
        n1 = f2fma(c3, s0, n1);
        n1 = f2fma(c4, a[m], n1);
        a[m] = n0; a[m1] = n1;
    }
}

__device__ __forceinline__ void read16u(const u64* __restrict__ src, int q, u64 a[16]) {
    const int rb = q << 4, rs = q & 15;
#pragma unroll
    for (int j = 0; j < 16; ++j) a[j] = src[rb | (j ^ rs)];
}

// write rotated-right-by-4 (k -> k+4), swizzled
__device__ __forceinline__ void write_rot4u(u64* __restrict__ dst, int q, const u64 a[16]) {
    const int lo = (q & 15) ^ (q >> 4);
    const int hi = q & 0x30;
#pragma unroll
    for (int j = 0; j < 16; ++j)
        dst[hi | (j << 6) | (lo ^ ((j & 3) << 2))] = a[j];
}

// 5-stage signed Walsh butterfly: W[lane] = sum_l v(l) * (-1)^pop(l & lane)
__device__ __forceinline__ float wht5(float v, int lane) {
#pragma unroll
    for (int i = 0; i < 5; ++i) {
        float t = __shfl_xor_sync(0xffffffffu, v, 1 << i);
        v = (lane & (1 << i)) ? (t - v) : (v + t);
    }
    return v;
}

__global__ void __launch_bounds__(NTH, 2)
qlstm_kernel(const float* __restrict__ inputs,
             const float* __restrict__ qparams,
             const float* __restrict__ Wf, const float* __restrict__ bf,
             const float* __restrict__ Wi, const float* __restrict__ bi,
             const float* __restrict__ Wg, const float* __restrict__ bg,
             const float* __restrict__ Wo, const float* __restrict__ bo,
             float* __restrict__ out)
{
    extern __shared__ char smem_raw[];
    Smem* S = (Smem*)smem_raw;

    const int tid  = threadIdx.x;
    const int b    = blockIdx.x;
    const int c    = tid >> 6;         // circuit 0..3
    const int q    = tid & 63;         // phys bits 4..9
    const int lane = tid & 31;
    const int wc   = (tid >> 5) & 1;   // warp within circuit

    // ---- one-time setup ----
    for (int i = tid; i < 420; i += NTH) {
        ((float*)S->sW)[i]        = Wf[i];
        ((float*)S->sW)[420 + i]  = Wi[i];
        ((float*)S->sW)[840 + i]  = Wg[i];
        ((float*)S->sW)[1260 + i] = Wo[i];
    }
    if (tid < HH) {
        S->sBias[0][tid] = bf[tid]; S->sBias[1][tid] = bi[tid];
        S->sBias[2][tid] = bg[tid]; S->sBias[3][tid] = bo[tid];
    }
    if (tid < 20) {
        int l = tid / 10, w = tid % 10;
        float tz = qparams[(l*10 + w)*3 + 0];
        float tx = qparams[(l*10 + w)*3 + 1];
        float ty = qparams[(l*10 + w)*3 + 2];
        float c1, s1, c2, s2, c3, s3;
        sincosf(0.5f*tz, &s1, &c1);
        sincosf(0.5f*tx, &s2, &c2);
        sincosf(0.5f*ty, &s3, &c3);
        float aAx =  c2*c1, aAy = -c2*s1;   // RX*RZ
        float bAx = -s2*s1, bAy = -s2*c1;
        float ax = c3*aAx - s3*bAx, ay = c3*aAy - s3*bAy;   // U = RY*RX*RZ
        float bx = s3*aAx + c3*bAx, by = s3*aAy + c3*bAy;
        if (l == 0) {
            S->sU0[w] = make_float4(ax, ay, bx, by);
        } else {
            S->sUc[w][0] = pk( ax,  ax);
            S->sUc[w][1] = pk(-ay,  ay);
            S->sUc[w][2] = pk(-bx, -bx);
            S->sUc[w][3] = pk(-by,  by);
            S->sUc[w][4] = pk( bx,  bx);
            S->sUc[w][5] = pk( ay, -ay);
        }
    }
    if (tid < DD) S->comb_x[0][tid] = inputs[(size_t)b*DD + tid];
    float cx_reg = 0.f, hx_reg = 0.f;
    __syncthreads();

    for (int t = 0; t < TT; ++t) {
        const int par = t & 1;
        float xpre = 0.f;
        const bool pf = (tid < DD) && (t + 1 < TT);
        if (pf) xpre = inputs[((size_t)((t+1)*BB) + b)*DD + tid];

        // ---- warp0 of circuit: pre-activation -> venc, then Ttab ----
        if (wc == 0) {
            float hj[HH];
#pragma unroll
            for (int j = 0; j < HH; ++j)
                hj[j] = __shfl_sync(0xffffffffu, hx_reg, j);
            if (lane < HH) {
                const float* wr = S->sW[c][lane];
                float acc0 = S->sBias[c][lane], acc1 = 0.f;
#pragma unroll
                for (int j = 0; j < DD; j += 2) {
                    acc0 = fmaf(wr[j],   S->comb_x[par][j],   acc0);
                    acc1 = fmaf(wr[j+1], S->comb_x[par][j+1], acc1);
                }
#pragma unroll
                for (int j = 0; j < HH; j += 2) {
                    acc0 = fmaf(wr[DD+j],   hj[j],   acc0);
                    acc1 = fmaf(wr[DD+j+1], hj[j+1], acc1);
                }
                float cc, ss;
                sincosf(0.5f*(acc0 + acc1), &ss, &cc);
                float4 U = S->sU0[lane];
                S->venc[c][lane][0] = pk(U.x*cc - U.z*ss, U.y*cc + U.w*ss);
                S->venc[c][lane][1] = pk(U.z*cc + U.x*ss, U.w*cc - U.y*ss);
            }
            __syncwarp();
            if (lane < 16) {   // wires 0-3 product table
                u64 t0 = S->venc[c][0][lane & 1];
                float tr = ulo(t0), ti = uhi(t0);
#pragma unroll
                for (int w = 1; w < 4; ++w) {
                    u64 tv = S->venc[c][w][(lane >> w) & 1];
                    float br = ulo(tv), bi = uhi(tv);
                    float nr = tr*br - ti*bi;
                    ti = tr*bi + ti*br; tr = nr;
                }
                S->Ttab[c][lane] = pk(tr, ti);
            }
        }
        cbar(c);

        // ---- Fused PA+P4: build ring^-1 state in regs, gates w0-3, rot4 ----
        {
            const int q0 = q & 1, q5 = (q >> 5) & 1;
            // x5..x9 from thread bits (ring^-1): x_w = y_{w-1} ^ y_w
            const int x5 = (q ^ (q >> 1)) & 1;
            const int x6 = ((q >> 1) ^ (q >> 2)) & 1;
            const int x7 = ((q >> 2) ^ (q >> 3)) & 1;
            const int x8 = ((q >> 3) ^ (q >> 4)) & 1;
            const int x9 = ((q >> 4) ^ (q >> 5)) & 1;
            u64 v5 = S->venc[c][5][x5], v6 = S->venc[c][6][x6];
            u64 v7 = S->venc[c][7][x7], v8 = S->venc[c][8][x8];
            u64 v9 = S->venc[c][9][x9];
            float pr = ulo(v5), pi = uhi(v5);
            { float br = ulo(v6), bi = uhi(v6);
              float nr = pr*br - pi*bi; pi = pr*bi + pi*br; pr = nr; }
            { float br = ulo(v7), bi = uhi(v7);
              float nr = pr*br - pi*bi; pi = pr*bi + pi*br; pr = nr; }
            { float br = ulo(v8), bi = uhi(v8);
              float nr = pr*br - pi*bi; pi = pr*bi + pi*br; pr = nr; }
            { float br = ulo(v9), bi = uhi(v9);
              float nr = pr*br - pi*bi; pi = pr*bi + pi*br; pr = nr; }
            // H(j3): x4 = j3 ^ q0
            u64 va = S->venc[c][4][q0];       // j3 = 0
            u64 vb = S->venc[c][4][q0 ^ 1];   // j3 = 1
            float h0r = ulo(va)*pr - uhi(va)*pi, h0i = ulo(va)*pi + uhi(va)*pr;
            float h1r = ulo(vb)*pr - uhi(vb)*pi, h1i = ulo(vb)*pi + uhi(vb)*pr;
            u64 H0r = pk(h0r, h0r), H0n = pk(-h0i, h0i);
            u64 H1r = pk(h1r, h1r), H1n = pk(-h1i, h1i);
            const int q5c = q5 ? 3 : 0;
            u64 a[16];
#pragma unroll
            for (int j = 0; j < 16; ++j) {
                u64 tv = S->Ttab[c][XLJ(j) ^ q5c];
                if (j < 8) a[j] = f2fma(H0r, tv, f2mul(H0n, dswp(tv)));
                else       a[j] = f2fma(H1r, tv, f2mul(H1n, dswp(tv)));
            }
            apply_bit16<0>(a, S->sUc[0]);
            apply_bit16<1>(a, S->sUc[1]);
            apply_bit16<2>(a, S->sUc[2]);
            apply_bit16<3>(a, S->sUc[3]);
            write_rot4u(S->sv1[c], q, a);
            cbar(c);
        }
        // ---- P5: L2 wires 4-7 (k=4 -> k=8) ----
        {
            u64 a[16];
            read16u(S->sv1[c], q, a);
            apply_bit16<0>(a, S->sUc[4]);
            apply_bit16<1>(a, S->sUc[5]);
            apply_bit16<2>(a, S->sUc[6]);
            apply_bit16<3>(a, S->sUc[7]);
            write_rot4u(S->sv0[c], q, a);
            cbar(c);
        }
        // ---- P6: L2 wires 8,9 + Walsh expectations ----
        {
            u64 a[16];
            read16u(S->sv0[c], q, a);
            apply_bit16<0>(a, S->sUc[8]);
            apply_bit16<1>(a, S->sUc[9]);
            float s0[8], d0[8];
#pragma unroll
            for (int k = 0; k < 8; ++k) {
                float x0 = ulo(a[2*k]),   y0 = uhi(a[2*k]);
                float x1 = ulo(a[2*k+1]), y1 = uhi(a[2*k+1]);
                float p0 = fmaf(x0, x0, y0*y0);
                float p1 = fmaf(x1, x1, y1*y1);
                s0[k] = p0 + p1; d0[k] = p0 - p1;
            }
            float ss[4], ds[4], dd[4];
#pragma unroll
            for (int k = 0; k < 4; ++k) {
                ss[k] = s0[2*k] + s0[2*k+1];
                ds[k] = d0[2*k] + d0[2*k+1];
                dd[k] = d0[2*k] - d0[2*k+1];
            }
            float S_C = ss[0] - ss[1] - ss[2] + ss[3];   // freq 0xC (w1..w7)
            float S_D = ds[0] - ds[1] - ds[2] + ds[3];   // freq 0xD (w8)
            float S_F = dd[0] - dd[1] - dd[2] + dd[3];   // freq 0xF (w9)
            float S_B = dd[0] + dd[1] - dd[2] - dd[3];   // freq 0xB (w0)
            float W_C = wht5(S_C, lane);
            float W_D = wht5(S_D, lane);
            float W_F = wht5(S_F, lane);
            float W_B = wht5(S_B, lane);
            float* qp = S->qpart[par][c][wc];
            if      (lane == 0)  qp[0] = W_C;
            else if (lane == 1)  qp[1] = W_C;
            else if (lane == 3)  qp[2] = W_C;
            else if (lane == 7)  qp[3] = W_C;
            else if (lane == 15) qp[4] = W_C;
            else if (lane == 31) {
                qp[5] = W_C; qp[6] = W_D; qp[7] = W_F; qp[8] = W_B;
            }
        }
        if (pf) S->comb_x[(t + 1) & 1][tid] = xpre;
        __syncthreads();

        // ---- LSTM cell update (lanes 0-9 of every warp, redundant) ----
        if (lane < HH) {
            const int h = lane;
            const int slot = (h == 0) ? 8 : (h <= 6 ? h - 1
                              : (h == 7 ? 5 : (h == 8 ? 6 : 7)));
            const float sg = (h >= 1 && h <= 6) ? 1.f : -1.f;
            float qv[4];
#pragma unroll
            for (int g = 0; g < 4; ++g)
                qv[g] = S->qpart[par][g][0][slot] + sg * S->qpart[par][g][1][slot];
            float fg = 1.f / (1.f + expf(-qv[0]));
            float ig = 1.f / (1.f + expf(-qv[1]));
            float gg = tanhf(qv[2]);
            float og = 1.f / (1.f + expf(-qv[3]));
            cx_reg = fg * cx_reg + ig * gg;
            hx_reg = og * tanhf(cx_reg);
            if (c == 0 && wc == 0)
                out[((size_t)(t*BB) + b)*HH + h] = hx_reg;
        }
        __syncwarp();
    }

    if (c == 0 && wc == 0 && lane < HH) {
        out[(size_t)TT*BB*HH + (size_t)b*HH + lane]                 = hx_reg;
        out[(size_t)TT*BB*HH + (size_t)BB*HH + (size_t)b*HH + lane] = cx_reg;
    }
}

extern "C" void kernel_launch(void* const* d_in, const int* in_sizes, int n_in,
                              void* d_out, int out_size) {
    (void)in_sizes; (void)n_in; (void)out_size;
    const float* inputs  = (const float*)d_in[0];
    const float* qparams = (const float*)d_in[1];
    const float* Wf = (const float*)d_in[2];
    const float* bf = (const float*)d_in[3];
    const float* Wi = (const float*)d_in[4];
    const float* bi = (const float*)d_in[5];
    const float* Wg = (const float*)d_in[6];
    const float* bg = (const float*)d_in[7];
    const float* Wo = (const float*)d_in[8];
    const float* bo = (const float*)d_in[9];
    float* out = (float*)d_out;
    cudaFuncSetAttribute(qlstm_kernel,
                         cudaFuncAttributeMaxDynamicSharedMemorySize,
                         (int)sizeof(Smem));
    qlstm_kernel<<<BB, NTH, sizeof(Smem)>>>(inputs, qparams, Wf, bf, Wi, bi,
                                            Wg, bg, Wo, bo, out);
}

// round 6
// speedup vs baseline: 1.0816x; 1.0816x over previous
#include <cuda_runtime.h>

// QLSTM on GB300. One CTA/batch element, warp-per-circuit, 32 amps/thread.
// Split re/im f32x2 packing: gates on non-pack wires are 8 clean FFMA2 per
// su2 (no register swaps). Per step/circuit only 2 passes touch smem:
//   Fused build: product state (encoding + L1 rotations + L1 CNOT ring via
//     ring^-1 index algebra) built in registers, L2 wires 0-4 applied,
//     scalar-swizzled transpose store.
//   P5: packed reload, L2 wires 5-9, probs + Walsh expectations (L2 ring
//     folded into parity masks).

#define TT 64
#define BB 256
#define DD 32
#define HH 10
#define NTH 128

typedef unsigned long long u64;

struct Smem {
    float  svr[4][1024];         // 16 KB statevector re
    float  svi[4][1024];         // 16 KB statevector im
    u64    sUc2[HH][7];          // clean-gate consts: AX,AY,nAY,BX,nBX,BY,nBY
    u64    sUi[2][6];            // pack-internal consts (wire0, wire5)
    float4 sU0[HH];              // layer-1 (ax,ay,bx,by)
    u64    venc[4][HH][2];       // per-wire 2-vectors (enc + L1 rot)
    u64    TrP[4][16];           // (T[m].re, T[m^3].re)
    u64    TiP[4][16];           // (T[m].im, T[m^3].im)
    float  sW[4][HH][42];
    float  sBias[4][HH];
    float  qpart[2][4][HH];
    float  comb_x[2][DD];
};

__device__ __forceinline__ u64 f2fma(u64 a, u64 b, u64 c) {
    u64 d;
    asm("fma.rn.f32x2 %0, %1, %2, %3;" : "=l"(d) : "l"(a), "l"(b), "l"(c));
    return d;
}
__device__ __forceinline__ u64 f2mul(u64 a, u64 b) {
    u64 d;
    asm("mul.rn.f32x2 %0, %1, %2;" : "=l"(d) : "l"(a), "l"(b));
    return d;
}
__device__ __forceinline__ u64 dswp(u64 a) {
    u64 r;
    asm("{\n\t.reg .b32 l, h;\n\tmov.b64 {l, h}, %1;\n\tmov.b64 %0, {h, l};\n\t}"
        : "=l"(r) : "l"(a));
    return r;
}
__device__ __forceinline__ u64 pk(float lo, float hi) {
    return (u64)__float_as_uint(lo) | ((u64)__float_as_uint(hi) << 32);
}
__device__ __forceinline__ float ulo(u64 v) { return __uint_as_float((unsigned)v); }
__device__ __forceinline__ float uhi(u64 v) { return __uint_as_float((unsigned)(v >> 32)); }

// low-4 wires linear map of even j (j=2k): contribution of k bits to (x0..x3)
__host__ __device__ constexpr int XLJ2(int k) {
    return ((k & 1) ? 0x6 : 0) ^ ((k & 2) ? 0xC : 0) ^ ((k & 4) ? 0x8 : 0);
}

// clean su2 on k-index bit B (pairs of packs; no swaps)
template<int B>
__device__ __forceinline__ void apply_clean(u64 rr[16], u64 ii[16],
                                            const u64* __restrict__ C) {
    u64 AX = C[0], AY = C[1], nAY = C[2], BX = C[3], nBX = C[4],
        BY = C[5], nBY = C[6];
#pragma unroll
    for (int m = 0; m < 16; ++m) {
        if (m & (1 << B)) continue;
        const int m1 = m | (1 << B);
        u64 r0 = rr[m], i0 = ii[m], r1 = rr[m1], i1 = ii[m1];
        rr[m]  = f2fma(AX, r0, f2fma(nAY, i0, f2fma(nBX, r1, f2mul(nBY, i1))));
        ii[m]  = f2fma(AY, r0, f2fma(AX,  i0, f2fma(BY,  r1, f2mul(nBX, i1))));
        rr[m1] = f2fma(BX, r0, f2fma(nBY, i0, f2fma(AX,  r1, f2mul(AY,  i1))));
        ii[m1] = f2fma(BY, r0, f2fma(BX,  i0, f2fma(nAY, r1, f2mul(AX,  i1))));
    }
}

// pack-internal su2 (the wire living in the f32x2 lanes)
__device__ __forceinline__ void apply_internal(u64 rr[16], u64 ii[16],
                                               const u64* __restrict__ C) {
    u64 AX = C[0], AYm = C[1], AYmn = C[2], BXm = C[3], BY = C[4], nBY = C[5];
#pragma unroll
    for (int m = 0; m < 16; ++m) {
        u64 sr = dswp(rr[m]), si = dswp(ii[m]);
        u64 nr = f2fma(AX, rr[m], f2fma(AYm,  ii[m], f2fma(BXm, sr, f2mul(nBY, si))));
        u64 ni = f2fma(AX, ii[m], f2fma(AYmn, rr[m], f2fma(BXm, si, f2mul(BY,  sr))));
        rr[m] = nr; ii[m] = ni;
    }
}

// 5-stage signed Walsh butterfly: W[lane] = sum_l v(l) * (-1)^pop(l & lane)
__device__ __forceinline__ float wht5(float v, int lane) {
#pragma unroll
    for (int i = 0; i < 5; ++i) {
        float t = __shfl_xor_sync(0xffffffffu, v, 1 << i);
        v = (lane & (1 << i)) ? (t - v) : (v + t);
    }
    return v;
}

__global__ void __launch_bounds__(NTH, 2)
qlstm_kernel(const float* __restrict__ inputs,
             const float* __restrict__ qparams,
             const float* __restrict__ Wf, const float* __restrict__ bf,
             const float* __restrict__ Wi, const float* __restrict__ bi,
             const float* __restrict__ Wg, const float* __restrict__ bg,
             const float* __restrict__ Wo, const float* __restrict__ bo,
             float* __restrict__ out)
{
    extern __shared__ char smem_raw[];
    Smem* S = (Smem*)smem_raw;

    const int tid  = threadIdx.x;
    const int b    = blockIdx.x;
    const int c    = tid >> 5;      // circuit == warp
    const int lane = tid & 31;
    const int q    = lane;
    float* svr = S->svr[c];
    float* svi = S->svi[c];

    // ---- one-time setup ----
    for (int i = tid; i < 420; i += NTH) {
        ((float*)S->sW)[i]        = Wf[i];
        ((float*)S->sW)[420 + i]  = Wi[i];
        ((float*)S->sW)[840 + i]  = Wg[i];
        ((float*)S->sW)[1260 + i] = Wo[i];
    }
    if (tid < HH) {
        S->sBias[0][tid] = bf[tid]; S->sBias[1][tid] = bi[tid];
        S->sBias[2][tid] = bg[tid]; S->sBias[3][tid] = bo[tid];
    }
    if (tid < 20) {
        int l = tid / 10, w = tid % 10;
        float tz = qparams[(l*10 + w)*3 + 0];
        float tx = qparams[(l*10 + w)*3 + 1];
        float ty = qparams[(l*10 + w)*3 + 2];
        float c1, s1, c2, s2, c3, s3;
        sincosf(0.5f*tz, &s1, &c1);
        sincosf(0.5f*tx, &s2, &c2);
        sincosf(0.5f*ty, &s3, &c3);
        float aAx =  c2*c1, aAy = -c2*s1;   // RX*RZ
        float bAx = -s2*s1, bAy = -s2*c1;
        float ax = c3*aAx - s3*bAx, ay = c3*aAy - s3*bAy;   // U = RY*RX*RZ
        float bx = s3*aAx + c3*bAx, by = s3*aAy + c3*bAy;
        if (l == 0) {
            S->sU0[w] = make_float4(ax, ay, bx, by);
        } else {
            S->sUc2[w][0] = pk( ax,  ax);
            S->sUc2[w][1] = pk( ay,  ay);
            S->sUc2[w][2] = pk(-ay, -ay);
            S->sUc2[w][3] = pk( bx,  bx);
            S->sUc2[w][4] = pk(-bx, -bx);
            S->sUc2[w][5] = pk( by,  by);
            S->sUc2[w][6] = pk(-by, -by);
            if (w == 0 || w == 5) {
                u64* I = S->sUi[w == 5];
                I[0] = pk( ax,  ax);
                I[1] = pk(-ay,  ay);
                I[2] = pk( ay, -ay);
                I[3] = pk(-bx,  bx);
                I[4] = pk( by,  by);
                I[5] = pk(-by, -by);
            }
        }
    }
    if (tid < DD) S->comb_x[0][tid] = inputs[(size_t)b*DD + tid];
    float cx_reg = 0.f, hx_reg = 0.f;
    __syncthreads();

    for (int t = 0; t < TT; ++t) {
        const int par = t & 1;
        float xpre = 0.f;
        const bool pf = (tid < DD) && (t + 1 < TT);
        if (pf) xpre = inputs[((size_t)((t+1)*BB) + b)*DD + tid];

        // ---- pre-activation -> per-wire vectors (lanes 0-9) ----
        float hj[HH];
#pragma unroll
        for (int j = 0; j < HH; ++j)
            hj[j] = __shfl_sync(0xffffffffu, hx_reg, j);
        if (lane < HH) {
            const float* wr = S->sW[c][lane];
            float a0 = S->sBias[c][lane], a1 = 0.f, a2 = 0.f, a3 = 0.f;
#pragma unroll
            for (int j = 0; j < DD; j += 4) {
                a0 = fmaf(wr[j],   S->comb_x[par][j],   a0);
                a1 = fmaf(wr[j+1], S->comb_x[par][j+1], a1);
                a2 = fmaf(wr[j+2], S->comb_x[par][j+2], a2);
                a3 = fmaf(wr[j+3], S->comb_x[par][j+3], a3);
            }
#pragma unroll
            for (int j = 0; j < 8; j += 4) {
                a0 = fmaf(wr[DD+j],   hj[j],   a0);
                a1 = fmaf(wr[DD+j+1], hj[j+1], a1);
                a2 = fmaf(wr[DD+j+2], hj[j+2], a2);
                a3 = fmaf(wr[DD+j+3], hj[j+3], a3);
            }
            a0 = fmaf(wr[40], hj[8], a0);
            a1 = fmaf(wr[41], hj[9], a1);
            float cc, ss;
            sincosf(0.5f*((a0 + a1) + (a2 + a3)), &ss, &cc);
            float4 U = S->sU0[lane];
            S->venc[c][lane][0] = pk(U.x*cc - U.z*ss, U.y*cc + U.w*ss);
            S->venc[c][lane][1] = pk(U.z*cc + U.x*ss, U.w*cc - U.y*ss);
        }
        __syncwarp();

        // ---- packed wires-0..3 product tables (lanes 0-15) ----
        if (lane < 16) {
            u64 v2v = S->venc[c][2][(lane >> 2) & 1];
            u64 v3v = S->venc[c][3][(lane >> 3) & 1];
            float Qr, Qi;
            { float ar=ulo(v2v), ai=uhi(v2v), br=ulo(v3v), bi=uhi(v3v);
              Qr = ar*br - ai*bi; Qi = ar*bi + ai*br; }
            u64 v0a = S->venc[c][0][lane & 1];
            u64 v1a = S->venc[c][1][(lane >> 1) & 1];
            u64 v0b = S->venc[c][0][(lane & 1) ^ 1];
            u64 v1b = S->venc[c][1][((lane >> 1) & 1) ^ 1];
            float Ar, Ai, Br, Bi;
            { float ar=ulo(v0a), ai=uhi(v0a), br=ulo(v1a), bi=uhi(v1a);
              Ar = ar*br - ai*bi; Ai = ar*bi + ai*br; }
            { float ar=ulo(v0b), ai=uhi(v0b), br=ulo(v1b), bi=uhi(v1b);
              Br = ar*br - ai*bi; Bi = ar*bi + ai*br; }
            float T0r = Ar*Qr - Ai*Qi, T0i = Ar*Qi + Ai*Qr;   // T[m]
            float T1r = Br*Qr - Bi*Qi, T1i = Br*Qi + Bi*Qr;   // T[m^3]
            S->TrP[c][lane] = pk(T0r, T1r);
            S->TiP[c][lane] = pk(T0i, T1i);
        }
        __syncwarp();

        // ---- Fused build (ring^-1 product state) + L2 wires 0-4 + store ----
        u64 rr[16], ii[16];
        {
            const int q0 = q & 1;
            const int q4c = (q & 16) ? 3 : 0;
            const int x6 = (q ^ (q >> 1)) & 1;
            const int x7 = ((q >> 1) ^ (q >> 2)) & 1;
            const int x8 = ((q >> 2) ^ (q >> 3)) & 1;
            const int x9 = ((q >> 3) ^ (q >> 4)) & 1;
            u64 p6 = S->venc[c][6][x6], p7 = S->venc[c][7][x7];
            u64 p8 = S->venc[c][8][x8], p9 = S->venc[c][9][x9];
            float Pr, Pi;
            { float ar=ulo(p6), ai=uhi(p6), br=ulo(p7), bi=uhi(p7);
              Pr = ar*br - ai*bi; Pi = ar*bi + ai*br; }
            { float br=ulo(p8), bi=uhi(p8);
              float nr = Pr*br - Pi*bi; Pi = Pr*bi + Pi*br; Pr = nr; }
            { float br=ulo(p9), bi=uhi(p9);
              float nr = Pr*br - Pi*bi; Pi = Pr*bi + Pi*br; Pr = nr; }
            u64 v40 = S->venc[c][4][0], v41 = S->venc[c][4][1];
            u64 wa  = S->venc[c][5][q0], wb = S->venc[c][5][q0 ^ 1];
            float PA0r, PA0i, PA1r, PA1i;
            { float br=ulo(v40), bi=uhi(v40);
              PA0r = Pr*br - Pi*bi; PA0i = Pr*bi + Pi*br; }
            { float br=ulo(v41), bi=uhi(v41);
              PA1r = Pr*br - Pi*bi; PA1i = Pr*bi + Pi*br; }
            float war = ulo(wa), wai = uhi(wa);
            float wbr = ulo(wb), wbi = uhi(wb);
            float H00r_ = PA0r*war - PA0i*wai, H00i_ = PA0r*wai + PA0i*war;
            float H10r_ = PA1r*war - PA1i*wai, H10i_ = PA1r*wai + PA1i*war;
            float H01r_ = PA1r*wbr - PA1i*wbi, H01i_ = PA1r*wbi + PA1i*wbr;
            float H11r_ = PA0r*wbr - PA0i*wbi, H11i_ = PA0r*wbi + PA0i*wbr;
            u64 H00r = pk(H00r_, H00r_), H00i = pk(H00i_, H00i_), H00n = pk(-H00i_, -H00i_);
            u64 H10r = pk(H10r_, H10r_), H10i = pk(H10i_, H10i_), H10n = pk(-H10i_, -H10i_);
            u64 H01r = pk(H01r_, H01r_), H01i = pk(H01i_, H01i_), H01n = pk(-H01i_, -H01i_);
            u64 H11r = pk(H11r_, H11r_), H11i = pk(H11i_, H11i_), H11n = pk(-H11i_, -H11i_);
#pragma unroll
            for (int k = 0; k < 16; ++k) {
                const int m = XLJ2(k & 7);
                u64 Trv = S->TrP[c][m ^ q4c];
                u64 Tiv = S->TiP[c][m ^ q4c];
                u64 hr, hi_, hn;
                if (k < 4)       { hr = H00r; hi_ = H00i; hn = H00n; }
                else if (k < 8)  { hr = H10r; hi_ = H10i; hn = H10n; }
                else if (k < 12) { hr = H01r; hi_ = H01i; hn = H01n; }
                else             { hr = H11r; hi_ = H11i; hn = H11n; }
                rr[k] = f2fma(hr, Trv, f2mul(hn, Tiv));
                ii[k] = f2fma(hr, Tiv, f2mul(hi_, Trv));
            }
        }
        apply_internal(rr, ii, S->sUi[0]);       // wire 0 (pack bit)
        apply_clean<0>(rr, ii, S->sUc2[1]);
        apply_clean<1>(rr, ii, S->sUc2[2]);
        apply_clean<2>(rr, ii, S->sUc2[3]);
        apply_clean<3>(rr, ii, S->sUc2[4]);
        // swizzled transpose store (scalar floats)
#pragma unroll
        for (int k = 0; k < 16; ++k) {
            const int j0 = 2*k, j1 = 2*k + 1;
            const int a0f = (j0 << 5) | (q ^ ((j0 << 1) & 30));
            const int a1f = (j1 << 5) | (q ^ ((j1 << 1) & 30));
            svr[a0f] = ulo(rr[k]); svr[a1f] = uhi(rr[k]);
            svi[a0f] = ulo(ii[k]); svi[a1f] = uhi(ii[k]);
        }
        __syncwarp();

        // ---- P5: packed reload, L2 wires 5-9, Walsh expectations ----
#pragma unroll
        for (int k = 0; k < 16; ++k) {
            const int fa = (q << 5) | ((2*k) ^ ((q << 1) & 30));
            rr[k] = *(const u64*)(svr + fa);
            ii[k] = *(const u64*)(svi + fa);
        }
        apply_internal(rr, ii, S->sUi[1]);       // wire 5 (pack bit)
        apply_clean<0>(rr, ii, S->sUc2[6]);
        apply_clean<1>(rr, ii, S->sUc2[7]);
        apply_clean<2>(rr, ii, S->sUc2[8]);
        apply_clean<3>(rr, ii, S->sUc2[9]);
        {
            float s0[16], d0[16];
#pragma unroll
            for (int k = 0; k < 16; ++k) {
                u64 pp = f2fma(rr[k], rr[k], f2mul(ii[k], ii[k]));
                s0[k] = ulo(pp) + uhi(pp);
                d0[k] = ulo(pp) - uhi(pp);
            }
            float Sh0 = ((s0[0]+s0[1])+(s0[2]+s0[3])) + ((s0[4]+s0[5])+(s0[6]+s0[7]))
                      + ((s0[8]+s0[9])+(s0[10]+s0[11])) + ((s0[12]+s0[13])+(s0[14]+s0[15]));
            float s1[8], d1[8];
#pragma unroll
            for (int k = 0; k < 8; ++k) {
                s1[k] = d0[2*k] + d0[2*k+1];
                d1[k] = d0[2*k] - d0[2*k+1];
            }
            float Sh1 = ((s1[0]+s1[1])+(s1[2]+s1[3])) + ((s1[4]+s1[5])+(s1[6]+s1[7]));
            float s2[4], d2[4];
#pragma unroll
            for (int k = 0; k < 4; ++k) {
                s2[k] = d1[2*k] + d1[2*k+1];
                d2[k] = d1[2*k] - d1[2*k+1];
            }
            float Sh3 = (s2[0]+s2[1]) + (s2[2]+s2[3]);
            float s3[2], d3[2];
            s3[0] = d2[0] + d2[1]; d3[0] = d2[0] - d2[1];
            s3[1] = d2[2] + d2[3]; d3[1] = d2[2] - d2[3];
            float Sh7  = s3[0] + s3[1];
            float ShF  = d3[0] + d3[1];
            float Sh1F = d3[0] - d3[1];

            float W0  = wht5(Sh0,  lane);
            float W1  = wht5(Sh1,  lane);
            float W3  = wht5(Sh3,  lane);
            float W7  = wht5(Sh7,  lane);
            float WF  = wht5(ShF,  lane);
            float W1F = wht5(Sh1F, lane);

            float* qp = S->qpart[par][c];
            if      (lane == 3)  qp[1] = W0;
            else if (lane == 7)  qp[2] = W0;
            else if (lane == 15) qp[3] = W0;
            else if (lane == 30) qp[0] = W1F;
            else if (lane == 31) {
                qp[4] = W0; qp[5] = W1; qp[6] = W3;
                qp[7] = W7; qp[8] = WF; qp[9] = W1F;
            }
        }
        if (pf) S->comb_x[(t + 1) & 1][tid] = xpre;
        __syncthreads();

        // ---- LSTM cell update (lanes 0-9 of every warp, redundant) ----
        if (lane < HH) {
            const int h = lane;
            float qf = S->qpart[par][0][h];
            float qi = S->qpart[par][1][h];
            float qg = S->qpart[par][2][h];
            float qo = S->qpart[par][3][h];
            float fg = 1.f / (1.f + expf(-qf));
            float ig = 1.f / (1.f + expf(-qi));
            float gg = tanhf(qg);
            float og = 1.f / (1.f + expf(-qo));
            cx_reg = fg * cx_reg + ig * gg;
            hx_reg = og * tanhf(cx_reg);
            if (c == 0)
                out[((size_t)(t*BB) + b)*HH + h] = hx_reg;
        }
        __syncwarp();
    }

    if (c == 0 && lane < HH) {
        out[(size_t)TT*BB*HH + (size_t)b*HH + lane]                 = hx_reg;
        out[(size_t)TT*BB*HH + (size_t)BB*HH + (size_t)b*HH + lane] = cx_reg;
    }
}

extern "C" void kernel_launch(void* const* d_in, const int* in_sizes, int n_in,
                              void* d_out, int out_size) {
    (void)in_sizes; (void)n_in; (void)out_size;
    const float* inputs  = (const float*)d_in[0];
    const float* qparams = (const float*)d_in[1];
    const float* Wf = (const float*)d_in[2];
    const float* bf = (const float*)d_in[3];
    const float* Wi = (const float*)d_in[4];
    const float* bi = (const float*)d_in[5];
    const float* Wg = (const float*)d_in[6];
    const float* bg = (const float*)d_in[7];
    const float* Wo = (const float*)d_in[8];
    const float* bo = (const float*)d_in[9];
    float* out = (float*)d_out;
    cudaFuncSetAttribute(qlstm_kernel,
                         cudaFuncAttributeMaxDynamicSharedMemorySize,
                         (int)sizeof(Smem));
    qlstm_kernel<<<BB, NTH, sizeof(Smem)>>>(inputs, qparams, Wf, bf, Wi, bi,
                                            Wg, bg, Wo, bo, out);
}

// round 7
// speedup vs baseline: 1.1894x; 1.0996x over previous
#include <cuda_runtime.h>

// QLSTM on GB300. One CTA/batch element, warp-per-circuit, 32 amps/thread.
// Split re/im f32x2 packing: gates on non-pack wires are 8 clean FFMA2 per
// su2 (no register swaps). Per step/circuit only 2 passes touch smem.
// R7: 3 CTAs/SM (launch_bounds cap 170 regs), fast-math transcendentals
// (__sincosf / MUFU.TANH sigmoid) to cut serial tail + register pressure.

#define TT 64
#define BB 256
#define DD 32
#define HH 10
#define NTH 128

typedef unsigned long long u64;

struct Smem {
    float  svr[4][1024];         // statevector re
    float  svi[4][1024];         // statevector im
    u64    sUc2[HH][7];          // clean-gate consts: AX,AY,nAY,BX,nBX,BY,nBY
    u64    sUi[2][6];            // pack-internal consts (wire0, wire5)
    float4 sU0[HH];              // layer-1 (ax,ay,bx,by)
    u64    venc[4][HH][2];       // per-wire 2-vectors (enc + L1 rot)
    u64    TrP[4][16];           // (T[m].re, T[m^3].re)
    u64    TiP[4][16];           // (T[m].im, T[m^3].im)
    float  sW[4][HH][42];
    float  sBias[4][HH];
    float  qpart[2][4][HH];
    float  comb_x[2][DD];
};

__device__ __forceinline__ u64 f2fma(u64 a, u64 b, u64 c) {
    u64 d;
    asm("fma.rn.f32x2 %0, %1, %2, %3;" : "=l"(d) : "l"(a), "l"(b), "l"(c));
    return d;
}
__device__ __forceinline__ u64 f2mul(u64 a, u64 b) {
    u64 d;
    asm("mul.rn.f32x2 %0, %1, %2;" : "=l"(d) : "l"(a), "l"(b));
    return d;
}
__device__ __forceinline__ u64 dswp(u64 a) {
    u64 r;
    asm("{\n\t.reg .b32 l, h;\n\tmov.b64 {l, h}, %1;\n\tmov.b64 %0, {h, l};\n\t}"
        : "=l"(r) : "l"(a));
    return r;
}
__device__ __forceinline__ u64 pk(float lo, float hi) {
    return (u64)__float_as_uint(lo) | ((u64)__float_as_uint(hi) << 32);
}
__device__ __forceinline__ float ulo(u64 v) { return __uint_as_float((unsigned)v); }
__device__ __forceinline__ float uhi(u64 v) { return __uint_as_float((unsigned)(v >> 32)); }

__device__ __forceinline__ float fast_tanh(float x) {
    float r;
    asm("tanh.approx.f32 %0, %1;" : "=f"(r) : "f"(x));
    return r;
}
__device__ __forceinline__ float fast_sigmoid(float x) {
    return fmaf(0.5f, fast_tanh(0.5f * x), 0.5f);
}

// low-4 wires linear map of even j (j=2k): contribution of k bits to (x0..x3)
__host__ __device__ constexpr int XLJ2(int k) {
    return ((k & 1) ? 0x6 : 0) ^ ((k & 2) ? 0xC : 0) ^ ((k & 4) ? 0x8 : 0);
}

// clean su2 on k-index bit B (pairs of packs; no swaps)
template<int B>
__device__ __forceinline__ void apply_clean(u64 rr[16], u64 ii[16],
                                            const u64* __restrict__ C) {
    u64 AX = C[0], AY = C[1], nAY = C[2], BX = C[3], nBX = C[4],
        BY = C[5], nBY = C[6];
#pragma unroll
    for (int m = 0; m < 16; ++m) {
        if (m & (1 << B)) continue;
        const int m1 = m | (1 << B);
        u64 r0 = rr[m], i0 = ii[m], r1 = rr[m1], i1 = ii[m1];
        rr[m]  = f2fma(AX, r0, f2fma(nAY, i0, f2fma(nBX, r1, f2mul(nBY, i1))));
        ii[m]  = f2fma(AY, r0, f2fma(AX,  i0, f2fma(BY,  r1, f2mul(nBX, i1))));
        rr[m1] = f2fma(BX, r0, f2fma(nBY, i0, f2fma(AX,  r1, f2mul(AY,  i1))));
        ii[m1] = f2fma(BY, r0, f2fma(BX,  i0, f2fma(nAY, r1, f2mul(AX,  i1))));
    }
}

// pack-internal su2 (the wire living in the f32x2 lanes)
__device__ __forceinline__ void apply_internal(u64 rr[16], u64 ii[16],
                                               const u64* __restrict__ C) {
    u64 AX = C[0], AYm = C[1], AYmn = C[2], BXm = C[3], BY = C[4], nBY = C[5];
#pragma unroll
    for (int m = 0; m < 16; ++m) {
        u64 sr = dswp(rr[m]), si = dswp(ii[m]);
        u64 nr = f2fma(AX, rr[m], f2fma(AYm,  ii[m], f2fma(BXm, sr, f2mul(nBY, si))));
        u64 ni = f2fma(AX, ii[m], f2fma(AYmn, rr[m], f2fma(BXm, si, f2mul(BY,  sr))));
        rr[m] = nr; ii[m] = ni;
    }
}

// 5-stage signed Walsh butterfly: W[lane] = sum_l v(l) * (-1)^pop(l & lane)
__device__ __forceinline__ float wht5(float v, int lane) {
#pragma unroll
    for (int i = 0; i < 5; ++i) {
        float t = __shfl_xor_sync(0xffffffffu, v, 1 << i);
        v = (lane & (1 << i)) ? (t - v) : (v + t);
    }
    return v;
}

__global__ void __launch_bounds__(NTH, 3)
qlstm_kernel(const float* __restrict__ inputs,
             const float* __restrict__ qparams,
             const float* __restrict__ Wf, const float* __restrict__ bf,
             const float* __restrict__ Wi, const float* __restrict__ bi,
             const float* __restrict__ Wg, const float* __restrict__ bg,
             const float* __restrict__ Wo, const float* __restrict__ bo,
             float* __restrict__ out)
{
    extern __shared__ char smem_raw[];
    Smem* S = (Smem*)smem_raw;

    const int tid  = threadIdx.x;
    const int b    = blockIdx.x;
    const int c    = tid >> 5;      // circuit == warp
    const int lane = tid & 31;
    const int q    = lane;
    float* svr = S->svr[c];
    float* svi = S->svi[c];

    // ---- one-time setup ----
    for (int i = tid; i < 420; i += NTH) {
        ((float*)S->sW)[i]        = Wf[i];
        ((float*)S->sW)[420 + i]  = Wi[i];
        ((float*)S->sW)[840 + i]  = Wg[i];
        ((float*)S->sW)[1260 + i] = Wo[i];
    }
    if (tid < HH) {
        S->sBias[0][tid] = bf[tid]; S->sBias[1][tid] = bi[tid];
        S->sBias[2][tid] = bg[tid]; S->sBias[3][tid] = bo[tid];
    }
    if (tid < 20) {
        int l = tid / 10, w = tid % 10;
        float tz = qparams[(l*10 + w)*3 + 0];
        float tx = qparams[(l*10 + w)*3 + 1];
        float ty = qparams[(l*10 + w)*3 + 2];
        float c1, s1, c2, s2, c3, s3;
        __sincosf(0.5f*tz, &s1, &c1);
        __sincosf(0.5f*tx, &s2, &c2);
        __sincosf(0.5f*ty, &s3, &c3);
        float aAx =  c2*c1, aAy = -c2*s1;   // RX*RZ
        float bAx = -s2*s1, bAy = -s2*c1;
        float ax = c3*aAx - s3*bAx, ay = c3*aAy - s3*bAy;   // U = RY*RX*RZ
        float bx = s3*aAx + c3*bAx, by = s3*aAy + c3*bAy;
        if (l == 0) {
            S->sU0[w] = make_float4(ax, ay, bx, by);
        } else {
            S->sUc2[w][0] = pk( ax,  ax);
            S->sUc2[w][1] = pk( ay,  ay);
            S->sUc2[w][2] = pk(-ay, -ay);
            S->sUc2[w][3] = pk( bx,  bx);
            S->sUc2[w][4] = pk(-bx, -bx);
            S->sUc2[w][5] = pk( by,  by);
            S->sUc2[w][6] = pk(-by, -by);
            if (w == 0 || w == 5) {
                u64* I = S->sUi[w == 5];
                I[0] = pk( ax,  ax);
                I[1] = pk(-ay,  ay);
                I[2] = pk( ay, -ay);
                I[3] = pk(-bx,  bx);
                I[4] = pk( by,  by);
                I[5] = pk(-by, -by);
            }
        }
    }
    if (tid < DD) S->comb_x[0][tid] = inputs[(size_t)b*DD + tid];
    float cx_reg = 0.f, hx_reg = 0.f;
    __syncthreads();

    for (int t = 0; t < TT; ++t) {
        const int par = t & 1;
        float xpre = 0.f;
        const bool pf = (tid < DD) && (t + 1 < TT);
        if (pf) xpre = inputs[((size_t)((t+1)*BB) + b)*DD + tid];

        // ---- pre-activation -> per-wire vectors (lanes 0-9) ----
        float hj[HH];
#pragma unroll
        for (int j = 0; j < HH; ++j)
            hj[j] = __shfl_sync(0xffffffffu, hx_reg, j);
        if (lane < HH) {
            const float* wr = S->sW[c][lane];
            float a0 = S->sBias[c][lane], a1 = 0.f, a2 = 0.f, a3 = 0.f;
#pragma unroll
            for (int j = 0; j < DD; j += 4) {
                a0 = fmaf(wr[j],   S->comb_x[par][j],   a0);
                a1 = fmaf(wr[j+1], S->comb_x[par][j+1], a1);
                a2 = fmaf(wr[j+2], S->comb_x[par][j+2], a2);
                a3 = fmaf(wr[j+3], S->comb_x[par][j+3], a3);
            }
#pragma unroll
            for (int j = 0; j < 8; j += 4) {
                a0 = fmaf(wr[DD+j],   hj[j],   a0);
                a1 = fmaf(wr[DD+j+1], hj[j+1], a1);
                a2 = fmaf(wr[DD+j+2], hj[j+2], a2);
                a3 = fmaf(wr[DD+j+3], hj[j+3], a3);
            }
            a0 = fmaf(wr[40], hj[8], a0);
            a1 = fmaf(wr[41], hj[9], a1);
            float cc, ss;
            __sincosf(0.5f*((a0 + a1) + (a2 + a3)), &ss, &cc);
            float4 U = S->sU0[lane];
            S->venc[c][lane][0] = pk(U.x*cc - U.z*ss, U.y*cc + U.w*ss);
            S->venc[c][lane][1] = pk(U.z*cc + U.x*ss, U.w*cc - U.y*ss);
        }
        __syncwarp();

        // ---- packed wires-0..3 product tables (lanes 0-15) ----
        if (lane < 16) {
            u64 v2v = S->venc[c][2][(lane >> 2) & 1];
            u64 v3v = S->venc[c][3][(lane >> 3) & 1];
            float Qr, Qi;
            { float ar=ulo(v2v), ai=uhi(v2v), br=ulo(v3v), bi=uhi(v3v);
              Qr = ar*br - ai*bi; Qi = ar*bi + ai*br; }
            u64 v0a = S->venc[c][0][lane & 1];
            u64 v1a = S->venc[c][1][(lane >> 1) & 1];
            u64 v0b = S->venc[c][0][(lane & 1) ^ 1];
            u64 v1b = S->venc[c][1][((lane >> 1) & 1) ^ 1];
            float Ar, Ai, Br, Bi;
            { float ar=ulo(v0a), ai=uhi(v0a), br=ulo(v1a), bi=uhi(v1a);
              Ar = ar*br - ai*bi; Ai = ar*bi + ai*br; }
            { float ar=ulo(v0b), ai=uhi(v0b), br=ulo(v1b), bi=uhi(v1b);
              Br = ar*br - ai*bi; Bi = ar*bi + ai*br; }
            float T0r = Ar*Qr - Ai*Qi, T0i = Ar*Qi + Ai*Qr;   // T[m]
            float T1r = Br*Qr - Bi*Qi, T1i = Br*Qi + Bi*Qr;   // T[m^3]
            S->TrP[c][lane] = pk(T0r, T1r);
            S->TiP[c][lane] = pk(T0i, T1i);
        }
        __syncwarp();

        // ---- Fused build (ring^-1 product state) + L2 wires 0-4 + store ----
        u64 rr[16], ii[16];
        {
            const int q0 = q & 1;
            const int q4c = (q & 16) ? 3 : 0;
            const int x6 = (q ^ (q >> 1)) & 1;
            const int x7 = ((q >> 1) ^ (q >> 2)) & 1;
            const int x8 = ((q >> 2) ^ (q >> 3)) & 1;
            const int x9 = ((q >> 3) ^ (q >> 4)) & 1;
            u64 p6 = S->venc[c][6][x6], p7 = S->venc[c][7][x7];
            u64 p8 = S->venc[c][8][x8], p9 = S->venc[c][9][x9];
            float Pr, Pi;
            { float ar=ulo(p6), ai=uhi(p6), br=ulo(p7), bi=uhi(p7);
              Pr = ar*br - ai*bi; Pi = ar*bi + ai*br; }
            { float br=ulo(p8), bi=uhi(p8);
              float nr = Pr*br - Pi*bi; Pi = Pr*bi + Pi*br; Pr = nr; }
            { float br=ulo(p9), bi=uhi(p9);
              float nr = Pr*br - Pi*bi; Pi = Pr*bi + Pi*br; Pr = nr; }
            u64 v40 = S->venc[c][4][0], v41 = S->venc[c][4][1];
            u64 wa  = S->venc[c][5][q0], wb = S->venc[c][5][q0 ^ 1];
            float PA0r, PA0i, PA1r, PA1i;
            { float br=ulo(v40), bi=uhi(v40);
              PA0r = Pr*br - Pi*bi; PA0i = Pr*bi + Pi*br; }
            { float br=ulo(v41), bi=uhi(v41);
              PA1r = Pr*br - Pi*bi; PA1i = Pr*bi + Pi*br; }
            float war = ulo(wa), wai = uhi(wa);
            float wbr = ulo(wb), wbi = uhi(wb);
            float H00r_ = PA0r*war - PA0i*wai, H00i_ = PA0r*wai + PA0i*war;
            float H10r_ = PA1r*war - PA1i*wai, H10i_ = PA1r*wai + PA1i*war;
            float H01r_ = PA1r*wbr - PA1i*wbi, H01i_ = PA1r*wbi + PA1i*wbr;
            float H11r_ = PA0r*wbr - PA0i*wbi, H11i_ = PA0r*wbi + PA0i*wbr;
            u64 H00r = pk(H00r_, H00r_), H00i = pk(H00i_, H00i_), H00n = pk(-H00i_, -H00i_);
            u64 H10r = pk(H10r_, H10r_), H10i = pk(H10i_, H10i_), H10n = pk(-H10i_, -H10i_);
            u64 H01r = pk(H01r_, H01r_), H01i = pk(H01i_, H01i_), H01n = pk(-H01i_, -H01i_);
            u64 H11r = pk(H11r_, H11r_), H11i = pk(H11i_, H11i_), H11n = pk(-H11i_, -H11i_);
#pragma unroll
            for (int k = 0; k < 16; ++k) {
                const int m = XLJ2(k & 7);
                u64 Trv = S->TrP[c][m ^ q4c];
                u64 Tiv = S->TiP[c][m ^ q4c];
                u64 hr, hi_, hn;
                if (k < 4)       { hr = H00r; hi_ = H00i; hn = H00n; }
                else if (k < 8)  { hr = H10r; hi_ = H10i; hn = H10n; }
                else if (k < 12) { hr = H01r; hi_ = H01i; hn = H01n; }
                else             { hr = H11r; hi_ = H11i; hn = H11n; }
                rr[k] = f2fma(hr, Trv, f2mul(hn, Tiv));
                ii[k] = f2fma(hr, Tiv, f2mul(hi_, Trv));
            }
        }
        apply_internal(rr, ii, S->sUi[0]);       // wire 0 (pack bit)
        apply_clean<0>(rr, ii, S->sUc2[1]);
        apply_clean<1>(rr, ii, S->sUc2[2]);
        apply_clean<2>(rr, ii, S->sUc2[3]);
        apply_clean<3>(rr, ii, S->sUc2[4]);
        // swizzled transpose store (scalar floats)
#pragma unroll
        for (int k = 0; k < 16; ++k) {
            const int j0 = 2*k, j1 = 2*k + 1;
            const int a0f = (j0 << 5) | (q ^ ((j0 << 1) & 30));
            const int a1f = (j1 << 5) | (q ^ ((j1 << 1) & 30));
            svr[a0f] = ulo(rr[k]); svr[a1f] = uhi(rr[k]);
            svi[a0f] = ulo(ii[k]); svi[a1f] = uhi(ii[k]);
        }
        __syncwarp();

        // ---- P5: packed reload, L2 wires 5-9, Walsh expectations ----
#pragma unroll
        for (int k = 0; k < 16; ++k) {
            const int fa = (q << 5) | ((2*k) ^ ((q << 1) & 30));
            rr[k] = *(const u64*)(svr + fa);
            ii[k] = *(const u64*)(svi + fa);
        }
        apply_internal(rr, ii, S->sUi[1]);       // wire 5 (pack bit)
        apply_clean<0>(rr, ii, S->sUc2[6]);
        apply_clean<1>(rr, ii, S->sUc2[7]);
        apply_clean<2>(rr, ii, S->sUc2[8]);
        apply_clean<3>(rr, ii, S->sUc2[9]);
        {
            float s0[16], d0[16];
#pragma unroll
            for (int k = 0; k < 16; ++k) {
                u64 pp = f2fma(rr[k], rr[k], f2mul(ii[k], ii[k]));
                s0[k] = ulo(pp) + uhi(pp);
                d0[k] = ulo(pp) - uhi(pp);
            }
            float Sh0 = ((s0[0]+s0[1])+(s0[2]+s0[3])) + ((s0[4]+s0[5])+(s0[6]+s0[7]))
                      + ((s0[8]+s0[9])+(s0[10]+s0[11])) + ((s0[12]+s0[13])+(s0[14]+s0[15]));
            float s1[8], d1[8];
#pragma unroll
            for (int k = 0; k < 8; ++k) {
                s1[k] = d0[2*k] + d0[2*k+1];
                d1[k] = d0[2*k] - d0[2*k+1];
            }
            float Sh1 = ((s1[0]+s1[1])+(s1[2]+s1[3])) + ((s1[4]+s1[5])+(s1[6]+s1[7]));
            float s2[4], d2[4];
#pragma unroll
            for (int k = 0; k < 4; ++k) {
                s2[k] = d1[2*k] + d1[2*k+1];
                d2[k] = d1[2*k] - d1[2*k+1];
            }
            float Sh3 = (s2[0]+s2[1]) + (s2[2]+s2[3]);
            float s3[2], d3[2];
            s3[0] = d2[0] + d2[1]; d3[0] = d2[0] - d2[1];
            s3[1] = d2[2] + d2[3]; d3[1] = d2[2] - d2[3];
            float Sh7  = s3[0] + s3[1];
            float ShF  = d3[0] + d3[1];
            float Sh1F = d3[0] - d3[1];

            float W0  = wht5(Sh0,  lane);
            float W1  = wht5(Sh1,  lane);
            float W3  = wht5(Sh3,  lane);
            float W7  = wht5(Sh7,  lane);
            float WF  = wht5(ShF,  lane);
            float W1F = wht5(Sh1F, lane);

            float* qp = S->qpart[par][c];
            if      (lane == 3)  qp[1] = W0;
            else if (lane == 7)  qp[2] = W0;
            else if (lane == 15) qp[3] = W0;
            else if (lane == 30) qp[0] = W1F;
            else if (lane == 31) {
                qp[4] = W0; qp[5] = W1; qp[6] = W3;
                qp[7] = W7; qp[8] = WF; qp[9] = W1F;
            }
        }
        if (pf) S->comb_x[(t + 1) & 1][tid] = xpre;
        __syncthreads();

        // ---- LSTM cell update (lanes 0-9 of every warp, redundant) ----
        if (lane < HH) {
            const int h = lane;
            float qf = S->qpart[par][0][h];
            float qi = S->qpart[par][1][h];
            float qg = S->qpart[par][2][h];
            float qo = S->qpart[par][3][h];
            float fg = fast_sigmoid(qf);
            float ig = fast_sigmoid(qi);
            float gg = fast_tanh(qg);
            float og = fast_sigmoid(qo);
            cx_reg = fg * cx_reg + ig * gg;
            hx_reg = og * fast_tanh(cx_reg);
            if (c == 0)
                out[((size_t)(t*BB) + b)*HH + h] = hx_reg;
        }
        __syncwarp();
    }

    if (c == 0 && lane < HH) {
        out[(size_t)TT*BB*HH + (size_t)b*HH + lane]                 = hx_reg;
        out[(size_t)TT*BB*HH + (size_t)BB*HH + (size_t)b*HH + lane] = cx_reg;
    }
}

extern "C" void kernel_launch(void* const* d_in, const int* in_sizes, int n_in,
                              void* d_out, int out_size) {
    (void)in_sizes; (void)n_in; (void)out_size;
    const float* inputs  = (const float*)d_in[0];
    const float* qparams = (const float*)d_in[1];
    const float* Wf = (const float*)d_in[2];
    const float* bf = (const float*)d_in[3];
    const float* Wi = (const float*)d_in[4];
    const float* bi = (const float*)d_in[5];
    const float* Wg = (const float*)d_in[6];
    const float* bg = (const float*)d_in[7];
    const float* Wo = (const float*)d_in[8];
    const float* bo = (const float*)d_in[9];
    float* out = (float*)d_out;
    cudaFuncSetAttribute(qlstm_kernel,
                         cudaFuncAttributeMaxDynamicSharedMemorySize,
                         (int)sizeof(Smem));
    qlstm_kernel<<<BB, NTH, sizeof(Smem)>>>(inputs, qparams, Wf, bf, Wi, bi,
                                            Wg, bg, Wo, bo, out);
}

// round 8
// speedup vs baseline: 1.4887x; 1.2516x over previous
#include <cuda_runtime.h>

// QLSTM on GB300. One CTA/batch element, warp-per-circuit, 32 amps/thread.
// Split re/im f32x2 packing + PHASE-NORMALIZED layer-2 gates:
//   each L2 gate is row-phase-normalized to M = [[A, -u+iv],[u+iv, A]], A real
//   (free since only a permutation + |.|^2 follow) -> clean su2 = 12 FFMA2,
//   pack-internal su2 = 8 ops.
// W.x precomputed for all 64 steps at setup (recurrence only needs W.h).

#define TT 64
#define BB 256
#define DD 32
#define HH 10
#define NTH 128

typedef unsigned long long u64;

struct Smem {
    float  svr[4][1024];         // statevector re (also setup scratch)
    float  svi[4][1024];         // statevector im
    u64    sUc2[HH][6];          // L2 gate consts: A2,U2,nU2,V2,nV2,Um
    float4 sU0[HH];              // layer-1 (ax,ay,bx,by)
    u64    venc[4][HH][2];       // per-wire 2-vectors (enc + L1 rot)
    u64    TrP[4][16];           // (T[m].re, T[m^3].re)
    u64    TiP[4][16];           // (T[m].im, T[m^3].im)
    float  sWx[TT][40];          // 0.5*(W.x + b) for all steps/gates/wires
    float  sWh[4][HH][HH];       // 0.5*W_h
    float  qpart[2][4][HH];
};

__device__ __forceinline__ u64 f2fma(u64 a, u64 b, u64 c) {
    u64 d;
    asm("fma.rn.f32x2 %0, %1, %2, %3;" : "=l"(d) : "l"(a), "l"(b), "l"(c));
    return d;
}
__device__ __forceinline__ u64 f2mul(u64 a, u64 b) {
    u64 d;
    asm("mul.rn.f32x2 %0, %1, %2;" : "=l"(d) : "l"(a), "l"(b));
    return d;
}
__device__ __forceinline__ u64 dswp(u64 a) {
    u64 r;
    asm("{\n\t.reg .b32 l, h;\n\tmov.b64 {l, h}, %1;\n\tmov.b64 %0, {h, l};\n\t}"
        : "=l"(r) : "l"(a));
    return r;
}
__device__ __forceinline__ u64 pk(float lo, float hi) {
    return (u64)__float_as_uint(lo) | ((u64)__float_as_uint(hi) << 32);
}
__device__ __forceinline__ float ulo(u64 v) { return __uint_as_float((unsigned)v); }
__device__ __forceinline__ float uhi(u64 v) { return __uint_as_float((unsigned)(v >> 32)); }

__device__ __forceinline__ float fast_tanh(float x) {
    float r;
    asm("tanh.approx.f32 %0, %1;" : "=f"(r) : "f"(x));
    return r;
}
__device__ __forceinline__ float fast_sigmoid(float x) {
    return fmaf(0.5f, fast_tanh(0.5f * x), 0.5f);
}

// low-4 wires linear map of even j (j=2k): contribution of k bits to (x0..x3)
__host__ __device__ constexpr int XLJ2(int k) {
    return ((k & 1) ? 0x6 : 0) ^ ((k & 2) ? 0xC : 0) ^ ((k & 4) ? 0x8 : 0);
}

// phase-normalized clean su2 on k-index bit B: 12 f2 ops
template<int B>
__device__ __forceinline__ void apply_clean(u64 rr[16], u64 ii[16],
                                            const u64* __restrict__ C) {
    u64 A2 = C[0], U2 = C[1], nU2 = C[2], V2 = C[3], nV2 = C[4];
#pragma unroll
    for (int m = 0; m < 16; ++m) {
        if (m & (1 << B)) continue;
        const int m1 = m | (1 << B);
        u64 r0 = rr[m], i0 = ii[m], r1 = rr[m1], i1 = ii[m1];
        rr[m]  = f2fma(A2, r0, f2fma(nU2, r1, f2mul(nV2, i1)));
        ii[m]  = f2fma(A2, i0, f2fma(V2,  r1, f2mul(nU2, i1)));
        rr[m1] = f2fma(A2, r1, f2fma(U2,  r0, f2mul(nV2, i0)));
        ii[m1] = f2fma(A2, i1, f2fma(V2,  r0, f2mul(U2,  i0)));
    }
}

// phase-normalized pack-internal su2: 8 ops
__device__ __forceinline__ void apply_internal(u64 rr[16], u64 ii[16],
                                               const u64* __restrict__ C) {
    u64 A2 = C[0], V2 = C[3], nV2 = C[4], Um = C[5];
#pragma unroll
    for (int m = 0; m < 16; ++m) {
        u64 sr = dswp(rr[m]), si = dswp(ii[m]);
        u64 nr = f2fma(A2, rr[m], f2fma(Um, sr, f2mul(nV2, si)));
        u64 ni = f2fma(A2, ii[m], f2fma(Um, si, f2mul(V2,  sr)));
        rr[m] = nr; ii[m] = ni;
    }
}

// 5-stage signed Walsh butterfly: W[lane] = sum_l v(l) * (-1)^pop(l & lane)
__device__ __forceinline__ float wht5(float v, int lane) {
#pragma unroll
    for (int i = 0; i < 5; ++i) {
        float t = __shfl_xor_sync(0xffffffffu, v, 1 << i);
        v = (lane & (1 << i)) ? (t - v) : (v + t);
    }
    return v;
}

__global__ void __launch_bounds__(NTH, 2)
qlstm_kernel(const float* __restrict__ inputs,
             const float* __restrict__ qparams,
             const float* __restrict__ Wf, const float* __restrict__ bf,
             const float* __restrict__ Wi, const float* __restrict__ bi,
             const float* __restrict__ Wg, const float* __restrict__ bg,
             const float* __restrict__ Wo, const float* __restrict__ bo,
             float* __restrict__ out)
{
    extern __shared__ char smem_raw[];
    Smem* S = (Smem*)smem_raw;

    const int tid  = threadIdx.x;
    const int b    = blockIdx.x;
    const int c    = tid >> 5;      // circuit == warp
    const int lane = tid & 31;
    const int q    = lane;
    float* svr = S->svr[c];
    float* svi = S->svi[c];

    const float* Ws[4] = {Wf, Wi, Wg, Wo};
    const float* Bs[4] = {bf, bi, bg, bo};

    // ---- setup: stage x into scratch (svr area), gate consts ----
    float* scratch = &S->svr[0][0];     // 4096 floats available, need 2048
    for (int i = tid; i < TT * DD; i += NTH)
        scratch[i] = inputs[((size_t)(i / DD) * BB + b) * DD + (i % DD)];

    if (tid < 20) {
        int l = tid / 10, w = tid % 10;
        float tz = qparams[(l*10 + w)*3 + 0];
        float tx = qparams[(l*10 + w)*3 + 1];
        float ty = qparams[(l*10 + w)*3 + 2];
        float c1, s1, c2, s2, c3, s3;
        __sincosf(0.5f*tz, &s1, &c1);
        __sincosf(0.5f*tx, &s2, &c2);
        __sincosf(0.5f*ty, &s3, &c3);
        float aAx =  c2*c1, aAy = -c2*s1;   // RX*RZ
        float bAx = -s2*s1, bAy = -s2*c1;
        float ax = c3*aAx - s3*bAx, ay = c3*aAy - s3*bAy;   // U = RY*RX*RZ
        float bx = s3*aAx + c3*bAx, by = s3*aAy + c3*bAy;
        if (l == 0) {
            S->sU0[w] = make_float4(ax, ay, bx, by);
        } else {
            // row-phase normalization: M = [[A, -u+iv],[u+iv, A]], A=|alpha|
            float n2 = ax*ax + ay*ay;
            float inv = rsqrtf(n2);
            float A = n2 * inv;
            float u = inv * (ax*bx - ay*by);
            float v = inv * (ax*by + ay*bx);
            S->sUc2[w][0] = pk( A,  A);
            S->sUc2[w][1] = pk( u,  u);
            S->sUc2[w][2] = pk(-u, -u);
            S->sUc2[w][3] = pk( v,  v);
            S->sUc2[w][4] = pk(-v, -v);
            S->sUc2[w][5] = pk(-u,  u);
        }
    }
    __syncthreads();

    // ---- setup: precompute 0.5*(W.x + b) for all steps ----
    if (tid < 120) {
        const int trio = tid / 40, pr = tid % 40;
        const int g = pr / 10, h = pr % 10;
        const float* Wrow = Ws[g] + h * 42;
        const float bias = Bs[g][h];
        float wreg[DD];
#pragma unroll
        for (int j = 0; j < DD; ++j) wreg[j] = Wrow[j];
        const int t0 = (trio == 0) ? 0 : (trio == 1) ? 22 : 44;
        const int t1 = (trio == 0) ? 22 : (trio == 1) ? 44 : TT;
        for (int t = t0; t < t1; ++t) {
            const float* xv = scratch + t * DD;
            float a0 = 0.f, a1 = 0.f, a2 = 0.f, a3 = 0.f;
#pragma unroll
            for (int j = 0; j < DD; j += 4) {
                a0 = fmaf(wreg[j],   xv[j],   a0);
                a1 = fmaf(wreg[j+1], xv[j+1], a1);
                a2 = fmaf(wreg[j+2], xv[j+2], a2);
                a3 = fmaf(wreg[j+3], xv[j+3], a3);
            }
            S->sWx[t][pr] = 0.5f * (((a0 + a1) + (a2 + a3)) + bias);
        }
    }
    if (tid < 40) {
        const int g = tid / 10, h = tid % 10;
        const float* Wrow = Ws[g] + h * 42 + DD;
#pragma unroll
        for (int j = 0; j < HH; ++j)
            S->sWh[g][h][j] = 0.5f * Wrow[j];
    }
    float cx_reg = 0.f, hx_reg = 0.f;
    __syncthreads();

    for (int t = 0; t < TT; ++t) {
        const int par = t & 1;

        // ---- pre-activation (h-part only) -> per-wire vectors (lanes 0-9) ----
        float hj[HH];
#pragma unroll
        for (int j = 0; j < HH; ++j)
            hj[j] = __shfl_sync(0xffffffffu, hx_reg, j);
        if (lane < HH) {
            float acc = S->sWx[t][c * 10 + lane];
            const float* wh = S->sWh[c][lane];
#pragma unroll
            for (int j = 0; j < HH; ++j)
                acc = fmaf(wh[j], hj[j], acc);
            float cc, ss;
            __sincosf(acc, &ss, &cc);
            float4 U = S->sU0[lane];
            S->venc[c][lane][0] = pk(U.x*cc - U.z*ss, U.y*cc + U.w*ss);
            S->venc[c][lane][1] = pk(U.z*cc + U.x*ss, U.w*cc - U.y*ss);
        }
        __syncwarp();

        // ---- packed wires-0..3 product tables (lanes 0-15) ----
        if (lane < 16) {
            u64 v2v = S->venc[c][2][(lane >> 2) & 1];
            u64 v3v = S->venc[c][3][(lane >> 3) & 1];
            float Qr, Qi;
            { float ar=ulo(v2v), ai=uhi(v2v), br=ulo(v3v), bi=uhi(v3v);
              Qr = ar*br - ai*bi; Qi = ar*bi + ai*br; }
            u64 v0a = S->venc[c][0][lane & 1];
            u64 v1a = S->venc[c][1][(lane >> 1) & 1];
            u64 v0b = S->venc[c][0][(lane & 1) ^ 1];
            u64 v1b = S->venc[c][1][((lane >> 1) & 1) ^ 1];
            float Ar, Ai, Br, Bi;
            { float ar=ulo(v0a), ai=uhi(v0a), br=ulo(v1a), bi=uhi(v1a);
              Ar = ar*br - ai*bi; Ai = ar*bi + ai*br; }
            { float ar=ulo(v0b), ai=uhi(v0b), br=ulo(v1b), bi=uhi(v1b);
              Br = ar*br - ai*bi; Bi = ar*bi + ai*br; }
            float T0r = Ar*Qr - Ai*Qi, T0i = Ar*Qi + Ai*Qr;   // T[m]
            float T1r = Br*Qr - Bi*Qi, T1i = Br*Qi + Bi*Qr;   // T[m^3]
            S->TrP[c][lane] = pk(T0r, T1r);
            S->TiP[c][lane] = pk(T0i, T1i);
        }
        __syncwarp();

        // ---- Fused build (ring^-1 product state) + L2 wires 0-4 + store ----
        u64 rr[16], ii[16];
        {
            const int q0 = q & 1;
            const int q4c = (q & 16) ? 3 : 0;
            const int x6 = (q ^ (q >> 1)) & 1;
            const int x7 = ((q >> 1) ^ (q >> 2)) & 1;
            const int x8 = ((q >> 2) ^ (q >> 3)) & 1;
            const int x9 = ((q >> 3) ^ (q >> 4)) & 1;
            u64 p6 = S->venc[c][6][x6], p7 = S->venc[c][7][x7];
            u64 p8 = S->venc[c][8][x8], p9 = S->venc[c][9][x9];
            float Pr, Pi;
            { float ar=ulo(p6), ai=uhi(p6), br=ulo(p7), bi=uhi(p7);
              Pr = ar*br - ai*bi; Pi = ar*bi + ai*br; }
            { float br=ulo(p8), bi=uhi(p8);
              float nr = Pr*br - Pi*bi; Pi = Pr*bi + Pi*br; Pr = nr; }
            { float br=ulo(p9), bi=uhi(p9);
              float nr = Pr*br - Pi*bi; Pi = Pr*bi + Pi*br; Pr = nr; }
            u64 v40 = S->venc[c][4][0], v41 = S->venc[c][4][1];
            u64 wa  = S->venc[c][5][q0], wb = S->venc[c][5][q0 ^ 1];
            float PA0r, PA0i, PA1r, PA1i;
            { float br=ulo(v40), bi=uhi(v40);
              PA0r = Pr*br - Pi*bi; PA0i = Pr*bi + Pi*br; }
            { float br=ulo(v41), bi=uhi(v41);
              PA1r = Pr*br - Pi*bi; PA1i = Pr*bi + Pi*br; }
            float war = ulo(wa), wai = uhi(wa);
            float wbr = ulo(wb), wbi = uhi(wb);
            float H00r_ = PA0r*war - PA0i*wai, H00i_ = PA0r*wai + PA0i*war;
            float H10r_ = PA1r*war - PA1i*wai, H10i_ = PA1r*wai + PA1i*war;
            float H01r_ = PA1r*wbr - PA1i*wbi, H01i_ = PA1r*wbi + PA1i*wbr;
            float H11r_ = PA0r*wbr - PA0i*wbi, H11i_ = PA0r*wbi + PA0i*wbr;
            u64 H00r = pk(H00r_, H00r_), H00i = pk(H00i_, H00i_), H00n = pk(-H00i_, -H00i_);
            u64 H10r = pk(H10r_, H10r_), H10i = pk(H10i_, H10i_), H10n = pk(-H10i_, -H10i_);
            u64 H01r = pk(H01r_, H01r_), H01i = pk(H01i_, H01i_), H01n = pk(-H01i_, -H01i_);
            u64 H11r = pk(H11r_, H11r_), H11i = pk(H11i_, H11i_), H11n = pk(-H11i_, -H11i_);
#pragma unroll
            for (int k = 0; k < 16; ++k) {
                const int m = XLJ2(k & 7);
                u64 Trv = S->TrP[c][m ^ q4c];
                u64 Tiv = S->TiP[c][m ^ q4c];
                u64 hr, hi_, hn;
                if (k < 4)       { hr = H00r; hi_ = H00i; hn = H00n; }
                else if (k < 8)  { hr = H10r; hi_ = H10i; hn = H10n; }
                else if (k < 12) { hr = H01r; hi_ = H01i; hn = H01n; }
                else             { hr = H11r; hi_ = H11i; hn = H11n; }
                rr[k] = f2fma(hr, Trv, f2mul(hn, Tiv));
                ii[k] = f2fma(hr, Tiv, f2mul(hi_, Trv));
            }
        }
        apply_internal(rr, ii, S->sUc2[0]);      // wire 0 (pack bit)
        apply_clean<0>(rr, ii, S->sUc2[1]);
        apply_clean<1>(rr, ii, S->sUc2[2]);
        apply_clean<2>(rr, ii, S->sUc2[3]);
        apply_clean<3>(rr, ii, S->sUc2[4]);
        // swizzled transpose store (scalar floats)
#pragma unroll
        for (int k = 0; k < 16; ++k) {
            const int j0 = 2*k, j1 = 2*k + 1;
            const int a0f = (j0 << 5) | (q ^ ((j0 << 1) & 30));
            const int a1f = (j1 << 5) | (q ^ ((j1 << 1) & 30));
            svr[a0f] = ulo(rr[k]); svr[a1f] = uhi(rr[k]);
            svi[a0f] = ulo(ii[k]); svi[a1f] = uhi(ii[k]);
        }
        __syncwarp();

        // ---- P5: packed reload, L2 wires 5-9, Walsh expectations ----
#pragma unroll
        for (int k = 0; k < 16; ++k) {
            const int fa = (q << 5) | ((2*k) ^ ((q << 1) & 30));
            rr[k] = *(const u64*)(svr + fa);
            ii[k] = *(const u64*)(svi + fa);
        }
        apply_internal(rr, ii, S->sUc2[5]);      // wire 5 (pack bit)
        apply_clean<0>(rr, ii, S->sUc2[6]);
        apply_clean<1>(rr, ii, S->sUc2[7]);
        apply_clean<2>(rr, ii, S->sUc2[8]);
        apply_clean<3>(rr, ii, S->sUc2[9]);
        {
            float s0[16], d0[16];
#pragma unroll
            for (int k = 0; k < 16; ++k) {
                u64 pp = f2fma(rr[k], rr[k], f2mul(ii[k], ii[k]));
                s0[k] = ulo(pp) + uhi(pp);
                d0[k] = ulo(pp) - uhi(pp);
            }
            float Sh0 = ((s0[0]+s0[1])+(s0[2]+s0[3])) + ((s0[4]+s0[5])+(s0[6]+s0[7]))
                      + ((s0[8]+s0[9])+(s0[10]+s0[11])) + ((s0[12]+s0[13])+(s0[14]+s0[15]));
            float s1[8], d1[8];
#pragma unroll
            for (int k = 0; k < 8; ++k) {
                s1[k] = d0[2*k] + d0[2*k+1];
                d1[k] = d0[2*k] - d0[2*k+1];
            }
            float Sh1 = ((s1[0]+s1[1])+(s1[2]+s1[3])) + ((s1[4]+s1[5])+(s1[6]+s1[7]));
            float s2[4], d2[4];
#pragma unroll
            for (int k = 0; k < 4; ++k) {
                s2[k] = d1[2*k] + d1[2*k+1];
                d2[k] = d1[2*k] - d1[2*k+1];
            }
            float Sh3 = (s2[0]+s2[1]) + (s2[2]+s2[3]);
            float s3[2], d3[2];
            s3[0] = d2[0] + d2[1]; d3[0] = d2[0] - d2[1];
            s3[1] = d2[2] + d2[3]; d3[1] = d2[2] - d2[3];
            float Sh7  = s3[0] + s3[1];
            float ShF  = d3[0] + d3[1];
            float Sh1F = d3[0] - d3[1];

            float W0  = wht5(Sh0,  lane);
            float W1  = wht5(Sh1,  lane);
            float W3  = wht5(Sh3,  lane);
            float W7  = wht5(Sh7,  lane);
            float WF  = wht5(ShF,  lane);
            float W1F = wht5(Sh1F, lane);

            float* qp = S->qpart[par][c];
            if      (lane == 3)  qp[1] = W0;
            else if (lane == 7)  qp[2] = W0;
            else if (lane == 15) qp[3] = W0;
            else if (lane == 30) qp[0] = W1F;
            else if (lane == 31) {
                qp[4] = W0; qp[5] = W1; qp[6] = W3;
                qp[7] = W7; qp[8] = WF; qp[9] = W1F;
            }
        }
        __syncthreads();

        // ---- LSTM cell update (lanes 0-9 of every warp, redundant) ----
        if (lane < HH) {
            const int h = lane;
            float qf = S->qpart[par][0][h];
            float qi = S->qpart[par][1][h];
            float qg = S->qpart[par][2][h];
            float qo = S->qpart[par][3][h];
            float fg = fast_sigmoid(qf);
            float ig = fast_sigmoid(qi);
            float gg = fast_tanh(qg);
            float og = fast_sigmoid(qo);
            cx_reg = fg * cx_reg + ig * gg;
            hx_reg = og * fast_tanh(cx_reg);
            if (c == 0)
                out[((size_t)(t*BB) + b)*HH + h] = hx_reg;
        }
        __syncwarp();
    }

    if (c == 0 && lane < HH) {
        out[(size_t)TT*BB*HH + (size_t)b*HH + lane]                 = hx_reg;
        out[(size_t)TT*BB*HH + (size_t)BB*HH + (size_t)b*HH + lane] = cx_reg;
    }
}

extern "C" void kernel_launch(void* const* d_in, const int* in_sizes, int n_in,
                              void* d_out, int out_size) {
    (void)in_sizes; (void)n_in; (void)out_size;
    const float* inputs  = (const float*)d_in[0];
    const float* qparams = (const float*)d_in[1];
    const float* Wf = (const float*)d_in[2];
    const float* bf = (const float*)d_in[3];
    const float* Wi = (const float*)d_in[4];
    const float* bi = (const float*)d_in[5];
    const float* Wg = (const float*)d_in[6];
    const float* bg = (const float*)d_in[7];
    const float* Wo = (const float*)d_in[8];
    const float* bo = (const float*)d_in[9];
    float* out = (float*)d_out;
    cudaFuncSetAttribute(qlstm_kernel,
                         cudaFuncAttributeMaxDynamicSharedMemorySize,
                         (int)sizeof(Smem));
    qlstm_kernel<<<BB, NTH, sizeof(Smem)>>>(inputs, qparams, Wf, bf, Wi, bi,
                                            Wg, bg, Wo, bo, out);
}

// round 9
// speedup vs baseline: 1.7057x; 1.1458x over previous
#include <cuda_runtime.h>

// QLSTM on GB300. One CTA/batch element, warp-per-circuit, 32 amps/thread.
// Split re/im f32x2 packing + phase-normalized L2 gates.
// R9: L2 gates on wires 0,1,2 are FOLDED INTO THE 16-ENTRY PRODUCT TABLE
// (they act purely on table-index bits): w0 = pack-local transform,
// w1/w2 = shfl-partner table transforms. Saves ~320 f2 ops/thread/step.
// Remaining in-register gates: w3,w4 (pre-transpose), w5 internal + w6-9
// (post-transpose), then probs + Walsh expectations.

#define TT 64
#define BB 256
#define DD 32
#define HH 10
#define NTH 128

typedef unsigned long long u64;

struct Smem {
    float  svr[4][1024];         // statevector re (also setup scratch)
    float  svi[4][1024];         // statevector im
    u64    sUc2[HH][6];          // L2 gate consts: A2,U2,nU2,V2,nV2,Um
    float4 sU0[HH];              // layer-1 (ax,ay,bx,by)
    u64    venc[4][HH][2];       // per-wire 2-vectors (enc + L1 rot)
    u64    TrP[4][16];           // transformed table packs (re)
    u64    TiP[4][16];           // transformed table packs (im)
    float  sWx[TT][40];          // 0.5*(W.x + b) for all steps/gates/wires
    float  sWh[4][HH][HH];       // 0.5*W_h
    float  qpart[2][4][HH];
};

__device__ __forceinline__ u64 f2fma(u64 a, u64 b, u64 c) {
    u64 d;
    asm("fma.rn.f32x2 %0, %1, %2, %3;" : "=l"(d) : "l"(a), "l"(b), "l"(c));
    return d;
}
__device__ __forceinline__ u64 f2mul(u64 a, u64 b) {
    u64 d;
    asm("mul.rn.f32x2 %0, %1, %2;" : "=l"(d) : "l"(a), "l"(b));
    return d;
}
__device__ __forceinline__ u64 dswp(u64 a) {
    u64 r;
    asm("{\n\t.reg .b32 l, h;\n\tmov.b64 {l, h}, %1;\n\tmov.b64 %0, {h, l};\n\t}"
        : "=l"(r) : "l"(a));
    return r;
}
__device__ __forceinline__ u64 pk(float lo, float hi) {
    return (u64)__float_as_uint(lo) | ((u64)__float_as_uint(hi) << 32);
}
__device__ __forceinline__ float ulo(u64 v) { return __uint_as_float((unsigned)v); }
__device__ __forceinline__ float uhi(u64 v) { return __uint_as_float((unsigned)(v >> 32)); }

__device__ __forceinline__ float fast_tanh(float x) {
    float r;
    asm("tanh.approx.f32 %0, %1;" : "=f"(r) : "f"(x));
    return r;
}
__device__ __forceinline__ float fast_sigmoid(float x) {
    return fmaf(0.5f, fast_tanh(0.5f * x), 0.5f);
}

// low-4 wires linear map of even j (j=2k): contribution of k bits to (x0..x3)
__host__ __device__ constexpr int XLJ2(int k) {
    return ((k & 1) ? 0x6 : 0) ^ ((k & 2) ? 0xC : 0) ^ ((k & 4) ? 0x8 : 0);
}

// phase-normalized clean su2 on k-index bit B: 12 f2 ops
template<int B>
__device__ __forceinline__ void apply_clean(u64 rr[16], u64 ii[16],
                                            const u64* __restrict__ C) {
    u64 A2 = C[0], U2 = C[1], nU2 = C[2], V2 = C[3], nV2 = C[4];
#pragma unroll
    for (int m = 0; m < 16; ++m) {
        if (m & (1 << B)) continue;
        const int m1 = m | (1 << B);
        u64 r0 = rr[m], i0 = ii[m], r1 = rr[m1], i1 = ii[m1];
        rr[m]  = f2fma(A2, r0, f2fma(nU2, r1, f2mul(nV2, i1)));
        ii[m]  = f2fma(A2, i0, f2fma(V2,  r1, f2mul(nU2, i1)));
        rr[m1] = f2fma(A2, r1, f2fma(U2,  r0, f2mul(nV2, i0)));
        ii[m1] = f2fma(A2, i1, f2fma(V2,  r0, f2mul(U2,  i0)));
    }
}

// phase-normalized pack-internal su2: 8 ops
__device__ __forceinline__ void apply_internal(u64 rr[16], u64 ii[16],
                                               const u64* __restrict__ C) {
    u64 A2 = C[0], V2 = C[3], nV2 = C[4], Um = C[5];
#pragma unroll
    for (int m = 0; m < 16; ++m) {
        u64 sr = dswp(rr[m]), si = dswp(ii[m]);
        u64 nr = f2fma(A2, rr[m], f2fma(Um, sr, f2mul(nV2, si)));
        u64 ni = f2fma(A2, ii[m], f2fma(Um, si, f2mul(V2,  sr)));
        rr[m] = nr; ii[m] = ni;
    }
}

// 5-stage signed Walsh butterfly: W[lane] = sum_l v(l) * (-1)^pop(l & lane)
__device__ __forceinline__ float wht5(float v, int lane) {
#pragma unroll
    for (int i = 0; i < 5; ++i) {
        float t = __shfl_xor_sync(0xffffffffu, v, 1 << i);
        v = (lane & (1 << i)) ? (t - v) : (v + t);
    }
    return v;
}

__global__ void __launch_bounds__(NTH, 2)
qlstm_kernel(const float* __restrict__ inputs,
             const float* __restrict__ qparams,
             const float* __restrict__ Wf, const float* __restrict__ bf,
             const float* __restrict__ Wi, const float* __restrict__ bi,
             const float* __restrict__ Wg, const float* __restrict__ bg,
             const float* __restrict__ Wo, const float* __restrict__ bo,
             float* __restrict__ out)
{
    extern __shared__ char smem_raw[];
    Smem* S = (Smem*)smem_raw;

    const int tid  = threadIdx.x;
    const int b    = blockIdx.x;
    const int c    = tid >> 5;      // circuit == warp
    const int lane = tid & 31;
    const int q    = lane;
    float* svr = S->svr[c];
    float* svi = S->svi[c];

    const float* Ws[4] = {Wf, Wi, Wg, Wo};
    const float* Bs[4] = {bf, bi, bg, bo};

    // ---- setup: stage x into scratch (svr area), gate consts ----
    float* scratch = &S->svr[0][0];
    for (int i = tid; i < TT * DD; i += NTH)
        scratch[i] = inputs[((size_t)(i / DD) * BB + b) * DD + (i % DD)];

    if (tid < 20) {
        int l = tid / 10, w = tid % 10;
        float tz = qparams[(l*10 + w)*3 + 0];
        float tx = qparams[(l*10 + w)*3 + 1];
        float ty = qparams[(l*10 + w)*3 + 2];
        float c1, s1, c2, s2, c3, s3;
        __sincosf(0.5f*tz, &s1, &c1);
        __sincosf(0.5f*tx, &s2, &c2);
        __sincosf(0.5f*ty, &s3, &c3);
        float aAx =  c2*c1, aAy = -c2*s1;   // RX*RZ
        float bAx = -s2*s1, bAy = -s2*c1;
        float ax = c3*aAx - s3*bAx, ay = c3*aAy - s3*bAy;   // U = RY*RX*RZ
        float bx = s3*aAx + c3*bAx, by = s3*aAy + c3*bAy;
        if (l == 0) {
            S->sU0[w] = make_float4(ax, ay, bx, by);
        } else {
            // row-phase normalization: M = [[A, -u+iv],[u+iv, A]], A=|alpha|
            float n2 = ax*ax + ay*ay;
            float inv = rsqrtf(n2);
            float A = n2 * inv;
            float u = inv * (ax*bx - ay*by);
            float v = inv * (ax*by + ay*bx);
            S->sUc2[w][0] = pk( A,  A);
            S->sUc2[w][1] = pk( u,  u);
            S->sUc2[w][2] = pk(-u, -u);
            S->sUc2[w][3] = pk( v,  v);
            S->sUc2[w][4] = pk(-v, -v);
            S->sUc2[w][5] = pk(-u,  u);
        }
    }
    __syncthreads();

    // ---- setup: precompute 0.5*(W.x + b) for all steps ----
    if (tid < 120) {
        const int trio = tid / 40, pr = tid % 40;
        const int g = pr / 10, h = pr % 10;
        const float* Wrow = Ws[g] + h * 42;
        const float bias = Bs[g][h];
        float wreg[DD];
#pragma unroll
        for (int j = 0; j < DD; ++j) wreg[j] = Wrow[j];
        const int t0 = (trio == 0) ? 0 : (trio == 1) ? 22 : 44;
        const int t1 = (trio == 0) ? 22 : (trio == 1) ? 44 : TT;
        for (int t = t0; t < t1; ++t) {
            const float* xv = scratch + t * DD;
            float a0 = 0.f, a1 = 0.f, a2 = 0.f, a3 = 0.f;
#pragma unroll
            for (int j = 0; j < DD; j += 4) {
                a0 = fmaf(wreg[j],   xv[j],   a0);
                a1 = fmaf(wreg[j+1], xv[j+1], a1);
                a2 = fmaf(wreg[j+2], xv[j+2], a2);
                a3 = fmaf(wreg[j+3], xv[j+3], a3);
            }
            S->sWx[t][pr] = 0.5f * (((a0 + a1) + (a2 + a3)) + bias);
        }
    }
    if (tid < 40) {
        const int g = tid / 10, h = tid % 10;
        const float* Wrow = Ws[g] + h * 42 + DD;
#pragma unroll
        for (int j = 0; j < HH; ++j)
            S->sWh[g][h][j] = 0.5f * Wrow[j];
    }
    float cx_reg = 0.f, hx_reg = 0.f;
    __syncthreads();

    for (int t = 0; t < TT; ++t) {
        const int par = t & 1;

        // ---- pre-activation (h-part only) -> per-wire vectors (lanes 0-9) ----
        float hj[HH];
#pragma unroll
        for (int j = 0; j < HH; ++j)
            hj[j] = __shfl_sync(0xffffffffu, hx_reg, j);
        if (lane < HH) {
            float acc = S->sWx[t][c * 10 + lane];
            const float* wh = S->sWh[c][lane];
#pragma unroll
            for (int j = 0; j < HH; ++j)
                acc = fmaf(wh[j], hj[j], acc);
            float cc, ss;
            __sincosf(acc, &ss, &cc);
            float4 U = S->sU0[lane];
            S->venc[c][lane][0] = pk(U.x*cc - U.z*ss, U.y*cc + U.w*ss);
            S->venc[c][lane][1] = pk(U.z*cc + U.x*ss, U.w*cc - U.y*ss);
        }
        __syncwarp();

        // ---- table stage (all 32 lanes compute; lanes 0-15 store) ----
        // base product table + L2 gates on wires 0,1,2 folded in
        {
            const int e = lane & 15;
            // base pack entries t0 = T[e], t1 = T[e^3]
            u64 v2v = S->venc[c][2][(e >> 2) & 1];
            u64 v3v = S->venc[c][3][(e >> 3) & 1];
            float Qr, Qi;
            { float ar=ulo(v2v), ai=uhi(v2v), br=ulo(v3v), bi=uhi(v3v);
              Qr = ar*br - ai*bi; Qi = ar*bi + ai*br; }
            u64 v0a = S->venc[c][0][e & 1];
            u64 v1a = S->venc[c][1][(e >> 1) & 1];
            u64 v0b = S->venc[c][0][(e & 1) ^ 1];
            u64 v1b = S->venc[c][1][((e >> 1) & 1) ^ 1];
            float Ar, Ai, Br, Bi;
            { float ar=ulo(v0a), ai=uhi(v0a), br=ulo(v1a), bi=uhi(v1a);
              Ar = ar*br - ai*bi; Ai = ar*bi + ai*br; }
            { float ar=ulo(v0b), ai=uhi(v0b), br=ulo(v1b), bi=uhi(v1b);
              Br = ar*br - ai*bi; Bi = ar*bi + ai*br; }
            float T0r = Ar*Qr - Ai*Qi, T0i = Ar*Qi + Ai*Qr;   // T[e]
            float T1r = Br*Qr - Bi*Qi, T1i = Br*Qi + Bi*Qr;   // T[e^3]

            // wire-0 fold (pack-local): u0 = A t0 - conj(w) t1 ; u1 = A t1 + w t0
            const float A0 = ulo(S->sUc2[0][0]);
            const float u0 = ulo(S->sUc2[0][1]);
            const float v0 = ulo(S->sUc2[0][3]);
            float u0r = A0*T0r - u0*T1r - v0*T1i;
            float u0i = A0*T0i + v0*T1r - u0*T1i;
            float u1r = A0*T1r + u0*T0r - v0*T0i;
            float u1i = A0*T1i + v0*T0r + u0*T0i;
            u64 Tr = pk(u0r, u1r), Ti = pk(u0i, u1i);

            // wire-1 fold: partner mask 6, side bit y1 = e0^e1
            {
                u64 A2 = S->sUc2[1][0], V2 = S->sUc2[1][3], nV2 = S->sUc2[1][4];
                u64 su = ((e ^ (e >> 1)) & 1) ? S->sUc2[1][1] : S->sUc2[1][2];
                u64 pre = __shfl_xor_sync(0xffffffffu, Tr, 6);
                u64 pim = __shfl_xor_sync(0xffffffffu, Ti, 6);
                u64 nTr = f2fma(A2, Tr, f2fma(su, pre, f2mul(nV2, pim)));
                u64 nTi = f2fma(A2, Ti, f2fma(V2,  pre, f2mul(su,  pim)));
                Tr = nTr; Ti = nTi;
            }
            // wire-2 fold: partner mask 0xC, side bit y2 = e0^e1^e2
            {
                u64 A2 = S->sUc2[2][0], V2 = S->sUc2[2][3], nV2 = S->sUc2[2][4];
                u64 su = ((e ^ (e >> 1) ^ (e >> 2)) & 1) ? S->sUc2[2][1] : S->sUc2[2][2];
                u64 pre = __shfl_xor_sync(0xffffffffu, Tr, 0xC);
                u64 pim = __shfl_xor_sync(0xffffffffu, Ti, 0xC);
                u64 nTr = f2fma(A2, Tr, f2fma(su, pre, f2mul(nV2, pim)));
                u64 nTi = f2fma(A2, Ti, f2fma(V2,  pre, f2mul(su,  pim)));
                Tr = nTr; Ti = nTi;
            }
            if (lane < 16) {
                S->TrP[c][e] = Tr;
                S->TiP[c][e] = Ti;
            }
        }
        __syncwarp();

        // ---- Fused build (ring^-1 product state, w0-2 already in table) ----
        u64 rr[16], ii[16];
        {
            const int q0 = q & 1;
            const int q4c = (q & 16) ? 3 : 0;
            const int x6 = (q ^ (q >> 1)) & 1;
            const int x7 = ((q >> 1) ^ (q >> 2)) & 1;
            const int x8 = ((q >> 2) ^ (q >> 3)) & 1;
            const int x9 = ((q >> 3) ^ (q >> 4)) & 1;
            u64 p6 = S->venc[c][6][x6], p7 = S->venc[c][7][x7];
            u64 p8 = S->venc[c][8][x8], p9 = S->venc[c][9][x9];
            float Pr, Pi;
            { float ar=ulo(p6), ai=uhi(p6), br=ulo(p7), bi=uhi(p7);
              Pr = ar*br - ai*bi; Pi = ar*bi + ai*br; }
            { float br=ulo(p8), bi=uhi(p8);
              float nr = Pr*br - Pi*bi; Pi = Pr*bi + Pi*br; Pr = nr; }
            { float br=ulo(p9), bi=uhi(p9);
              float nr = Pr*br - Pi*bi; Pi = Pr*bi + Pi*br; Pr = nr; }
            u64 v40 = S->venc[c][4][0], v41 = S->venc[c][4][1];
            u64 wa  = S->venc[c][5][q0], wb = S->venc[c][5][q0 ^ 1];
            float PA0r, PA0i, PA1r, PA1i;
            { float br=ulo(v40), bi=uhi(v40);
              PA0r = Pr*br - Pi*bi; PA0i = Pr*bi + Pi*br; }
            { float br=ulo(v41), bi=uhi(v41);
              PA1r = Pr*br - Pi*bi; PA1i = Pr*bi + Pi*br; }
            float war = ulo(wa), wai = uhi(wa);
            float wbr = ulo(wb), wbi = uhi(wb);
            float H00r_ = PA0r*war - PA0i*wai, H00i_ = PA0r*wai + PA0i*war;
            float H10r_ = PA1r*war - PA1i*wai, H10i_ = PA1r*wai + PA1i*war;
            float H01r_ = PA1r*wbr - PA1i*wbi, H01i_ = PA1r*wbi + PA1i*wbr;
            float H11r_ = PA0r*wbr - PA0i*wbi, H11i_ = PA0r*wbi + PA0i*wbr;
            u64 H00r = pk(H00r_, H00r_), H00i = pk(H00i_, H00i_), H00n = pk(-H00i_, -H00i_);
            u64 H10r = pk(H10r_, H10r_), H10i = pk(H10i_, H10i_), H10n = pk(-H10i_, -H10i_);
            u64 H01r = pk(H01r_, H01r_), H01i = pk(H01i_, H01i_), H01n = pk(-H01i_, -H01i_);
            u64 H11r = pk(H11r_, H11r_), H11i = pk(H11i_, H11i_), H11n = pk(-H11i_, -H11i_);
#pragma unroll
            for (int k = 0; k < 16; ++k) {
                const int m = XLJ2(k & 7);
                u64 Trv = S->TrP[c][m ^ q4c];
                u64 Tiv = S->TiP[c][m ^ q4c];
                u64 hr, hi_, hn;
                if (k < 4)       { hr = H00r; hi_ = H00i; hn = H00n; }
                else if (k < 8)  { hr = H10r; hi_ = H10i; hn = H10n; }
                else if (k < 12) { hr = H01r; hi_ = H01i; hn = H01n; }
                else             { hr = H11r; hi_ = H11i; hn = H11n; }
                rr[k] = f2fma(hr, Trv, f2mul(hn, Tiv));
                ii[k] = f2fma(hr, Tiv, f2mul(hi_, Trv));
            }
        }
        // wires 3,4 (register bits 2,3 of k)
        apply_clean<2>(rr, ii, S->sUc2[3]);
        apply_clean<3>(rr, ii, S->sUc2[4]);
        // swizzled transpose store (scalar floats)
#pragma unroll
        for (int k = 0; k < 16; ++k) {
            const int j0 = 2*k, j1 = 2*k + 1;
            const int a0f = (j0 << 5) | (q ^ ((j0 << 1) & 30));
            const int a1f = (j1 << 5) | (q ^ ((j1 << 1) & 30));
            svr[a0f] = ulo(rr[k]); svr[a1f] = uhi(rr[k]);
            svi[a0f] = ulo(ii[k]); svi[a1f] = uhi(ii[k]);
        }
        __syncwarp();

        // ---- P5: packed reload, L2 wires 5-9, Walsh expectations ----
#pragma unroll
        for (int k = 0; k < 16; ++k) {
            const int fa = (q << 5) | ((2*k) ^ ((q << 1) & 30));
            rr[k] = *(const u64*)(svr + fa);
            ii[k] = *(const u64*)(svi + fa);
        }
        apply_internal(rr, ii, S->sUc2[5]);      // wire 5 (pack bit)
        apply_clean<0>(rr, ii, S->sUc2[6]);
        apply_clean<1>(rr, ii, S->sUc2[7]);
        apply_clean<2>(rr, ii, S->sUc2[8]);
        apply_clean<3>(rr, ii, S->sUc2[9]);
        {
            float s0[16], d0[16];
#pragma unroll
            for (int k = 0; k < 16; ++k) {
                u64 pp = f2fma(rr[k], rr[k], f2mul(ii[k], ii[k]));
                s0[k] = ulo(pp) + uhi(pp);
                d0[k] = ulo(pp) - uhi(pp);
            }
            float Sh0 = ((s0[0]+s0[1])+(s0[2]+s0[3])) + ((s0[4]+s0[5])+(s0[6]+s0[7]))
                      + ((s0[8]+s0[9])+(s0[10]+s0[11])) + ((s0[12]+s0[13])+(s0[14]+s0[15]));
            float s1[8], d1[8];
#pragma unroll
            for (int k = 0; k < 8; ++k) {
                s1[k] = d0[2*k] + d0[2*k+1];
                d1[k] = d0[2*k] - d0[2*k+1];
            }
            float Sh1 = ((s1[0]+s1[1])+(s1[2]+s1[3])) + ((s1[4]+s1[5])+(s1[6]+s1[7]));
            float s2[4], d2[4];
#pragma unroll
            for (int k = 0; k < 4; ++k) {
                s2[k] = d1[2*k] + d1[2*k+1];
                d2[k] = d1[2*k] - d1[2*k+1];
            }
            float Sh3 = (s2[0]+s2[1]) + (s2[2]+s2[3]);
            float s3[2], d3[2];
            s3[0] = d2[0] + d2[1]; d3[0] = d2[0] - d2[1];
            s3[1] = d2[2] + d2[3]; d3[1] = d2[2] - d2[3];
            float Sh7  = s3[0] + s3[1];
            float ShF  = d3[0] + d3[1];
            float Sh1F = d3[0] - d3[1];

            float W0  = wht5(Sh0,  lane);
            float W1  = wht5(Sh1,  lane);
            float W3  = wht5(Sh3,  lane);
            float W7  = wht5(Sh7,  lane);
            float WF  = wht5(ShF,  lane);
            float W1F = wht5(Sh1F, lane);

            float* qp = S->qpart[par][c];
            if      (lane == 3)  qp[1] = W0;
            else if (lane == 7)  qp[2] = W0;
            else if (lane == 15) qp[3] = W0;
            else if (lane == 30) qp[0] = W1F;
            else if (lane == 31) {
                qp[4] = W0; qp[5] = W1; qp[6] = W3;
                qp[7] = W7; qp[8] = WF; qp[9] = W1F;
            }
        }
        __syncthreads();

        // ---- LSTM cell update (lanes 0-9 of every warp, redundant) ----
        if (lane < HH) {
            const int h = lane;
            float qf = S->qpart[par][0][h];
            float qi = S->qpart[par][1][h];
            float qg = S->qpart[par][2][h];
            float qo = S->qpart[par][3][h];
            float fg = fast_sigmoid(qf);
            float ig = fast_sigmoid(qi);
            float gg = fast_tanh(qg);
            float og = fast_sigmoid(qo);
            cx_reg = fg * cx_reg + ig * gg;
            hx_reg = og * fast_tanh(cx_reg);
            if (c == 0)
                out[((size_t)(t*BB) + b)*HH + h] = hx_reg;
        }
        __syncwarp();
    }

    if (c == 0 && lane < HH) {
        out[(size_t)TT*BB*HH + (size_t)b*HH + lane]                 = hx_reg;
        out[(size_t)TT*BB*HH + (size_t)BB*HH + (size_t)b*HH + lane] = cx_reg;
    }
}

extern "C" void kernel_launch(void* const* d_in, const int* in_sizes, int n_in,
                              void* d_out, int out_size) {
    (void)in_sizes; (void)n_in; (void)out_size;
    const float* inputs  = (const float*)d_in[0];
    const float* qparams = (const float*)d_in[1];
    const float* Wf = (const float*)d_in[2];
    const float* bf = (const float*)d_in[3];
    const float* Wi = (const float*)d_in[4];
    const float* bi = (const float*)d_in[5];
    const float* Wg = (const float*)d_in[6];
    const float* bg = (const float*)d_in[7];
    const float* Wo = (const float*)d_in[8];
    const float* bo = (const float*)d_in[9];
    float* out = (float*)d_out;
    cudaFuncSetAttribute(qlstm_kernel,
                         cudaFuncAttributeMaxDynamicSharedMemorySize,
                         (int)sizeof(Smem));
    qlstm_kernel<<<BB, NTH, sizeof(Smem)>>>(inputs, qparams, Wf, bf, Wi, bi,
                                            Wg, bg, Wo, bo, out);
}

// round 10
// speedup vs baseline: 1.8194x; 1.0667x over previous
#include <cuda_runtime.h>

// QLSTM on GB300. One CTA/batch element, warp-per-circuit, 32 amps/thread.
// Split re/im f32x2 packing + phase-normalized L2 gates.
// R9: L2 wires 0,1,2 folded into the 16-entry product table.
// R10: L2 wire 4 folded into the H quad (k3 only selects H class -> gate is
// a 2x2 complex rotation on 4 scalars, replacing 96 f2 ops); table merged to
// ulonglong2 (LDS.128 broadcasts); dual-accumulator pre-activation.
// Remaining in-register gates: w3 (pre-transpose), w5 internal + w6-9
// (post-transpose), then probs + Walsh expectations.

#define TT 64
#define BB 256
#define DD 32
#define HH 10
#define NTH 128

typedef unsigned long long u64;

struct Smem {
    float      svr[4][1024];     // statevector re (also setup scratch)
    float      svi[4][1024];     // statevector im
    ulonglong2 TT2[4][16];       // table packs (Tr, Ti)
    u64        sUc2[HH][6];      // L2 gate consts: A2,U2,nU2,V2,nV2,Um
    float4     sU0[HH];          // layer-1 (ax,ay,bx,by)
    u64        venc[4][HH][2];   // per-wire 2-vectors (enc + L1 rot)
    float      sWx[TT][40];      // 0.5*(W.x + b) for all steps/gates/wires
    float      sWh[4][HH][HH];   // 0.5*W_h
    float      qpart[2][4][HH];
};

__device__ __forceinline__ u64 f2fma(u64 a, u64 b, u64 c) {
    u64 d;
    asm("fma.rn.f32x2 %0, %1, %2, %3;" : "=l"(d) : "l"(a), "l"(b), "l"(c));
    return d;
}
__device__ __forceinline__ u64 f2mul(u64 a, u64 b) {
    u64 d;
    asm("mul.rn.f32x2 %0, %1, %2;" : "=l"(d) : "l"(a), "l"(b));
    return d;
}
__device__ __forceinline__ u64 dswp(u64 a) {
    u64 r;
    asm("{\n\t.reg .b32 l, h;\n\tmov.b64 {l, h}, %1;\n\tmov.b64 %0, {h, l};\n\t}"
        : "=l"(r) : "l"(a));
    return r;
}
__device__ __forceinline__ u64 pk(float lo, float hi) {
    return (u64)__float_as_uint(lo) | ((u64)__float_as_uint(hi) << 32);
}
__device__ __forceinline__ float ulo(u64 v) { return __uint_as_float((unsigned)v); }
__device__ __forceinline__ float uhi(u64 v) { return __uint_as_float((unsigned)(v >> 32)); }

__device__ __forceinline__ float fast_tanh(float x) {
    float r;
    asm("tanh.approx.f32 %0, %1;" : "=f"(r) : "f"(x));
    return r;
}
__device__ __forceinline__ float fast_sigmoid(float x) {
    return fmaf(0.5f, fast_tanh(0.5f * x), 0.5f);
}

// low-4 wires linear map of even j (j=2k): contribution of k bits to (x0..x3)
__host__ __device__ constexpr int XLJ2(int k) {
    return ((k & 1) ? 0x6 : 0) ^ ((k & 2) ? 0xC : 0) ^ ((k & 4) ? 0x8 : 0);
}

// phase-normalized clean su2 on k-index bit B: 12 f2 ops
template<int B>
__device__ __forceinline__ void apply_clean(u64 rr[16], u64 ii[16],
                                            const u64* __restrict__ C) {
    u64 A2 = C[0], U2 = C[1], nU2 = C[2], V2 = C[3], nV2 = C[4];
#pragma unroll
    for (int m = 0; m < 16; ++m) {
        if (m & (1 << B)) continue;
        const int m1 = m | (1 << B);
        u64 r0 = rr[m], i0 = ii[m], r1 = rr[m1], i1 = ii[m1];
        rr[m]  = f2fma(A2, r0, f2fma(nU2, r1, f2mul(nV2, i1)));
        ii[m]  = f2fma(A2, i0, f2fma(V2,  r1, f2mul(nU2, i1)));
        rr[m1] = f2fma(A2, r1, f2fma(U2,  r0, f2mul(nV2, i0)));
        ii[m1] = f2fma(A2, i1, f2fma(V2,  r0, f2mul(U2,  i0)));
    }
}

// phase-normalized pack-internal su2: 8 ops
__device__ __forceinline__ void apply_internal(u64 rr[16], u64 ii[16],
                                               const u64* __restrict__ C) {
    u64 A2 = C[0], V2 = C[3], nV2 = C[4], Um = C[5];
#pragma unroll
    for (int m = 0; m < 16; ++m) {
        u64 sr = dswp(rr[m]), si = dswp(ii[m]);
        u64 nr = f2fma(A2, rr[m], f2fma(Um, sr, f2mul(nV2, si)));
        u64 ni = f2fma(A2, ii[m], f2fma(Um, si, f2mul(V2,  sr)));
        rr[m] = nr; ii[m] = ni;
    }
}

// 5-stage signed Walsh butterfly: W[lane] = sum_l v(l) * (-1)^pop(l & lane)
__device__ __forceinline__ float wht5(float v, int lane) {
#pragma unroll
    for (int i = 0; i < 5; ++i) {
        float t = __shfl_xor_sync(0xffffffffu, v, 1 << i);
        v = (lane & (1 << i)) ? (t - v) : (v + t);
    }
    return v;
}

__global__ void __launch_bounds__(NTH, 2)
qlstm_kernel(const float* __restrict__ inputs,
             const float* __restrict__ qparams,
             const float* __restrict__ Wf, const float* __restrict__ bf,
             const float* __restrict__ Wi, const float* __restrict__ bi,
             const float* __restrict__ Wg, const float* __restrict__ bg,
             const float* __restrict__ Wo, const float* __restrict__ bo,
             float* __restrict__ out)
{
    extern __shared__ char smem_raw[];
    Smem* S = (Smem*)smem_raw;

    const int tid  = threadIdx.x;
    const int b    = blockIdx.x;
    const int c    = tid >> 5;      // circuit == warp
    const int lane = tid & 31;
    const int q    = lane;
    float* svr = S->svr[c];
    float* svi = S->svi[c];

    const float* Ws[4] = {Wf, Wi, Wg, Wo};
    const float* Bs[4] = {bf, bi, bg, bo};

    // ---- setup: stage x into scratch (svr area), gate consts ----
    float* scratch = &S->svr[0][0];
    for (int i = tid; i < TT * DD; i += NTH)
        scratch[i] = inputs[((size_t)(i / DD) * BB + b) * DD + (i % DD)];

    if (tid < 20) {
        int l = tid / 10, w = tid % 10;
        float tz = qparams[(l*10 + w)*3 + 0];
        float tx = qparams[(l*10 + w)*3 + 1];
        float ty = qparams[(l*10 + w)*3 + 2];
        float c1, s1, c2, s2, c3, s3;
        __sincosf(0.5f*tz, &s1, &c1);
        __sincosf(0.5f*tx, &s2, &c2);
        __sincosf(0.5f*ty, &s3, &c3);
        float aAx =  c2*c1, aAy = -c2*s1;   // RX*RZ
        float bAx = -s2*s1, bAy = -s2*c1;
        float ax = c3*aAx - s3*bAx, ay = c3*aAy - s3*bAy;   // U = RY*RX*RZ
        float bx = s3*aAx + c3*bAx, by = s3*aAy + c3*bAy;
        if (l == 0) {
            S->sU0[w] = make_float4(ax, ay, bx, by);
        } else {
            // row-phase normalization: M = [[A, -u+iv],[u+iv, A]], A=|alpha|
            float n2 = ax*ax + ay*ay;
            float inv = rsqrtf(n2);
            float A = n2 * inv;
            float u = inv * (ax*bx - ay*by);
            float v = inv * (ax*by + ay*bx);
            S->sUc2[w][0] = pk( A,  A);
            S->sUc2[w][1] = pk( u,  u);
            S->sUc2[w][2] = pk(-u, -u);
            S->sUc2[w][3] = pk( v,  v);
            S->sUc2[w][4] = pk(-v, -v);
            S->sUc2[w][5] = pk(-u,  u);
        }
    }
    __syncthreads();

    // ---- setup: precompute 0.5*(W.x + b) for all steps ----
    if (tid < 120) {
        const int trio = tid / 40, pr = tid % 40;
        const int g = pr / 10, h = pr % 10;
        const float* Wrow = Ws[g] + h * 42;
        const float bias = Bs[g][h];
        float wreg[DD];
#pragma unroll
        for (int j = 0; j < DD; ++j) wreg[j] = Wrow[j];
        const int t0 = (trio == 0) ? 0 : (trio == 1) ? 22 : 44;
        const int t1 = (trio == 0) ? 22 : (trio == 1) ? 44 : TT;
        for (int t = t0; t < t1; ++t) {
            const float* xv = scratch + t * DD;
            float a0 = 0.f, a1 = 0.f, a2 = 0.f, a3 = 0.f;
#pragma unroll
            for (int j = 0; j < DD; j += 4) {
                a0 = fmaf(wreg[j],   xv[j],   a0);
                a1 = fmaf(wreg[j+1], xv[j+1], a1);
                a2 = fmaf(wreg[j+2], xv[j+2], a2);
                a3 = fmaf(wreg[j+3], xv[j+3], a3);
            }
            S->sWx[t][pr] = 0.5f * (((a0 + a1) + (a2 + a3)) + bias);
        }
    }
    if (tid < 40) {
        const int g = tid / 10, h = tid % 10;
        const float* Wrow = Ws[g] + h * 42 + DD;
#pragma unroll
        for (int j = 0; j < HH; ++j)
            S->sWh[g][h][j] = 0.5f * Wrow[j];
    }
    float cx_reg = 0.f, hx_reg = 0.f;
    __syncthreads();

    for (int t = 0; t < TT; ++t) {
        const int par = t & 1;

        // ---- pre-activation (h-part only) -> per-wire vectors (lanes 0-9) ----
        float hj[HH];
#pragma unroll
        for (int j = 0; j < HH; ++j)
            hj[j] = __shfl_sync(0xffffffffu, hx_reg, j);
        if (lane < HH) {
            float acc0 = S->sWx[t][c * 10 + lane], acc1 = 0.f;
            const float* wh = S->sWh[c][lane];
#pragma unroll
            for (int j = 0; j < HH; j += 2) {
                acc0 = fmaf(wh[j],   hj[j],   acc0);
                acc1 = fmaf(wh[j+1], hj[j+1], acc1);
            }
            float cc, ss;
            __sincosf(acc0 + acc1, &ss, &cc);
            float4 U = S->sU0[lane];
            S->venc[c][lane][0] = pk(U.x*cc - U.z*ss, U.y*cc + U.w*ss);
            S->venc[c][lane][1] = pk(U.z*cc + U.x*ss, U.w*cc - U.y*ss);
        }
        __syncwarp();

        // ---- table stage (all 32 lanes compute; lanes 0-15 store) ----
        // base product table + L2 gates on wires 0,1,2 folded in
        {
            const int e = lane & 15;
            // base pack entries t0 = T[e], t1 = T[e^3]
            u64 v2v = S->venc[c][2][(e >> 2) & 1];
            u64 v3v = S->venc[c][3][(e >> 3) & 1];
            float Qr, Qi;
            { float ar=ulo(v2v), ai=uhi(v2v), br=ulo(v3v), bi=uhi(v3v);
              Qr = ar*br - ai*bi; Qi = ar*bi + ai*br; }
            u64 v0a = S->venc[c][0][e & 1];
            u64 v1a = S->venc[c][1][(e >> 1) & 1];
            u64 v0b = S->venc[c][0][(e & 1) ^ 1];
            u64 v1b = S->venc[c][1][((e >> 1) & 1) ^ 1];
            float Ar, Ai, Br, Bi;
            { float ar=ulo(v0a), ai=uhi(v0a), br=ulo(v1a), bi=uhi(v1a);
              Ar = ar*br - ai*bi; Ai = ar*bi + ai*br; }
            { float ar=ulo(v0b), ai=uhi(v0b), br=ulo(v1b), bi=uhi(v1b);
              Br = ar*br - ai*bi; Bi = ar*bi + ai*br; }
            float T0r = Ar*Qr - Ai*Qi, T0i = Ar*Qi + Ai*Qr;   // T[e]
            float T1r = Br*Qr - Bi*Qi, T1i = Br*Qi + Bi*Qr;   // T[e^3]

            // wire-0 fold (pack-local): u0 = A t0 - conj(w) t1 ; u1 = A t1 + w t0
            const float A0 = ulo(S->sUc2[0][0]);
            const float u0 = ulo(S->sUc2[0][1]);
            const float v0 = ulo(S->sUc2[0][3]);
            float u0r = A0*T0r - u0*T1r - v0*T1i;
            float u0i = A0*T0i + v0*T1r - u0*T1i;
            float u1r = A0*T1r + u0*T0r - v0*T0i;
            float u1i = A0*T1i + v0*T0r + u0*T0i;
            u64 Tr = pk(u0r, u1r), Ti = pk(u0i, u1i);

            // wire-1 fold: partner mask 6, side bit y1 = e0^e1
            {
                u64 A2 = S->sUc2[1][0], V2 = S->sUc2[1][3], nV2 = S->sUc2[1][4];
                u64 su = ((e ^ (e >> 1)) & 1) ? S->sUc2[1][1] : S->sUc2[1][2];
                u64 pre = __shfl_xor_sync(0xffffffffu, Tr, 6);
                u64 pim = __shfl_xor_sync(0xffffffffu, Ti, 6);
                u64 nTr = f2fma(A2, Tr, f2fma(su, pre, f2mul(nV2, pim)));
                u64 nTi = f2fma(A2, Ti, f2fma(V2,  pre, f2mul(su,  pim)));
                Tr = nTr; Ti = nTi;
            }
            // wire-2 fold: partner mask 0xC, side bit y2 = e0^e1^e2
            {
                u64 A2 = S->sUc2[2][0], V2 = S->sUc2[2][3], nV2 = S->sUc2[2][4];
                u64 su = ((e ^ (e >> 1) ^ (e >> 2)) & 1) ? S->sUc2[2][1] : S->sUc2[2][2];
                u64 pre = __shfl_xor_sync(0xffffffffu, Tr, 0xC);
                u64 pim = __shfl_xor_sync(0xffffffffu, Ti, 0xC);
                u64 nTr = f2fma(A2, Tr, f2fma(su, pre, f2mul(nV2, pim)));
                u64 nTi = f2fma(A2, Ti, f2fma(V2,  pre, f2mul(su,  pim)));
                Tr = nTr; Ti = nTi;
            }
            if (lane < 16)
                S->TT2[c][e] = make_ulonglong2(Tr, Ti);
        }
        __syncwarp();

        // ---- Fused build (ring^-1 product state, w0-2 in table, w4 in H) ----
        u64 rr[16], ii[16];
        {
            const int q0 = q & 1;
            const int q4c = (q & 16) ? 3 : 0;
            const int x6 = (q ^ (q >> 1)) & 1;
            const int x7 = ((q >> 1) ^ (q >> 2)) & 1;
            const int x8 = ((q >> 2) ^ (q >> 3)) & 1;
            const int x9 = ((q >> 3) ^ (q >> 4)) & 1;
            u64 p6 = S->venc[c][6][x6], p7 = S->venc[c][7][x7];
            u64 p8 = S->venc[c][8][x8], p9 = S->venc[c][9][x9];
            float Pr, Pi;
            { float ar=ulo(p6), ai=uhi(p6), br=ulo(p7), bi=uhi(p7);
              Pr = ar*br - ai*bi; Pi = ar*bi + ai*br; }
            { float br=ulo(p8), bi=uhi(p8);
              float nr = Pr*br - Pi*bi; Pi = Pr*bi + Pi*br; Pr = nr; }
            { float br=ulo(p9), bi=uhi(p9);
              float nr = Pr*br - Pi*bi; Pi = Pr*bi + Pi*br; Pr = nr; }
            u64 v40 = S->venc[c][4][0], v41 = S->venc[c][4][1];
            u64 wa  = S->venc[c][5][q0], wb = S->venc[c][5][q0 ^ 1];
            float PA0r, PA0i, PA1r, PA1i;
            { float br=ulo(v40), bi=uhi(v40);
              PA0r = Pr*br - Pi*bi; PA0i = Pr*bi + Pi*br; }
            { float br=ulo(v41), bi=uhi(v41);
              PA1r = Pr*br - Pi*bi; PA1i = Pr*bi + Pi*br; }
            float war = ulo(wa), wai = uhi(wa);
            float wbr = ulo(wb), wbi = uhi(wb);
            float H00r_ = PA0r*war - PA0i*wai, H00i_ = PA0r*wai + PA0i*war;
            float H10r_ = PA1r*war - PA1i*wai, H10i_ = PA1r*wai + PA1i*war;
            float H01r_ = PA1r*wbr - PA1i*wbi, H01i_ = PA1r*wbi + PA1i*wbr;
            float H11r_ = PA0r*wbr - PA0i*wbi, H11i_ = PA0r*wbi + PA0i*wbr;

            // ---- wire-4 gate folded into H quad (k3 flip: H00<->H01, H10<->H11)
            // m-side (k3=0): H' = A*H - u*Hp - iv-cross ; m1-side: H' = A*H + u*Hp ...
            {
                const float A4 = ulo(S->sUc2[4][0]);
                const float u4 = ulo(S->sUc2[4][1]);
                const float v4 = ulo(S->sUc2[4][3]);
                float n00r = A4*H00r_ - u4*H01r_ - v4*H01i_;
                float n00i = A4*H00i_ + v4*H01r_ - u4*H01i_;
                float n01r = A4*H01r_ + u4*H00r_ - v4*H00i_;
                float n01i = A4*H01i_ + v4*H00r_ + u4*H00i_;
                float n10r = A4*H10r_ - u4*H11r_ - v4*H11i_;
                float n10i = A4*H10i_ + v4*H11r_ - u4*H11i_;
                float n11r = A4*H11r_ + u4*H10r_ - v4*H10i_;
                float n11i = A4*H11i_ + v4*H10r_ + u4*H10i_;
                H00r_ = n00r; H00i_ = n00i; H01r_ = n01r; H01i_ = n01i;
                H10r_ = n10r; H10i_ = n10i; H11r_ = n11r; H11i_ = n11i;
            }

            u64 H00r = pk(H00r_, H00r_), H00i = pk(H00i_, H00i_), H00n = pk(-H00i_, -H00i_);
            u64 H10r = pk(H10r_, H10r_), H10i = pk(H10i_, H10i_), H10n = pk(-H10i_, -H10i_);
            u64 H01r = pk(H01r_, H01r_), H01i = pk(H01i_, H01i_), H01n = pk(-H01i_, -H01i_);
            u64 H11r = pk(H11r_, H11r_), H11i = pk(H11i_, H11i_), H11n = pk(-H11i_, -H11i_);
#pragma unroll
            for (int k = 0; k < 16; ++k) {
                const int m = XLJ2(k & 7);
                ulonglong2 tv = S->TT2[c][m ^ q4c];
                u64 Trv = tv.x, Tiv = tv.y;
                u64 hr, hi_, hn;
                if (k < 4)       { hr = H00r; hi_ = H00i; hn = H00n; }
                else if (k < 8)  { hr = H10r; hi_ = H10i; hn = H10n; }
                else if (k < 12) { hr = H01r; hi_ = H01i; hn = H01n; }
                else             { hr = H11r; hi_ = H11i; hn = H11n; }
                rr[k] = f2fma(hr, Trv, f2mul(hn, Tiv));
                ii[k] = f2fma(hr, Tiv, f2mul(hi_, Trv));
            }
        }
        // wire 3 (register bit 2 of k); wire 4 already folded into H
        apply_clean<2>(rr, ii, S->sUc2[3]);
        // swizzled transpose store (scalar floats)
#pragma unroll
        for (int k = 0; k < 16; ++k) {
            const int j0 = 2*k, j1 = 2*k + 1;
            const int a0f = (j0 << 5) | (q ^ ((j0 << 1) & 30));
            const int a1f = (j1 << 5) | (q ^ ((j1 << 1) & 30));
            svr[a0f] = ulo(rr[k]); svr[a1f] = uhi(rr[k]);
            svi[a0f] = ulo(ii[k]); svi[a1f] = uhi(ii[k]);
        }
        __syncwarp();

        // ---- P5: packed reload, L2 wires 5-9, Walsh expectations ----
#pragma unroll
        for (int k = 0; k < 16; ++k) {
            const int fa = (q << 5) | ((2*k) ^ ((q << 1) & 30));
            rr[k] = *(const u64*)(svr + fa);
            ii[k] = *(const u64*)(svi + fa);
        }
        apply_internal(rr, ii, S->sUc2[5]);      // wire 5 (pack bit)
        apply_clean<0>(rr, ii, S->sUc2[6]);
        apply_clean<1>(rr, ii, S->sUc2[7]);
        apply_clean<2>(rr, ii, S->sUc2[8]);
        apply_clean<3>(rr, ii, S->sUc2[9]);
        {
            float s0[16], d0[16];
#pragma unroll
            for (int k = 0; k < 16; ++k) {
                u64 pp = f2fma(rr[k], rr[k], f2mul(ii[k], ii[k]));
                s0[k] = ulo(pp) + uhi(pp);
                d0[k] = ulo(pp) - uhi(pp);
            }
            float Sh0 = ((s0[0]+s0[1])+(s0[2]+s0[3])) + ((s0[4]+s0[5])+(s0[6]+s0[7]))
                      + ((s0[8]+s0[9])+(s0[10]+s0[11])) + ((s0[12]+s0[13])+(s0[14]+s0[15]));
            float s1[8], d1[8];
#pragma unroll
            for (int k = 0; k < 8; ++k) {
                s1[k] = d0[2*k] + d0[2*k+1];
                d1[k] = d0[2*k] - d0[2*k+1];
            }
            float Sh1 = ((s1[0]+s1[1])+(s1[2]+s1[3])) + ((s1[4]+s1[5])+(s1[6]+s1[7]));
            float s2[4], d2[4];
#pragma unroll
            for (int k = 0; k < 4; ++k) {
                s2[k] = d1[2*k] + d1[2*k+1];
                d2[k] = d1[2*k] - d1[2*k+1];
            }
            float Sh3 = (s2[0]+s2[1]) + (s2[2]+s2[3]);
            float s3[2], d3[2];
            s3[0] = d2[0] + d2[1]; d3[0] = d2[0] - d2[1];
            s3[1] = d2[2] + d2[3]; d3[1] = d2[2] - d2[3];
            float Sh7  = s3[0] + s3[1];
            float ShF  = d3[0] + d3[1];
            float Sh1F = d3[0] - d3[1];

            float W0  = wht5(Sh0,  lane);
            float W1  = wht5(Sh1,  lane);
            float W3  = wht5(Sh3,  lane);
            float W7  = wht5(Sh7,  lane);
            float WF  = wht5(ShF,  lane);
            float W1F = wht5(Sh1F, lane);

            float* qp = S->qpart[par][c];
            if      (lane == 3)  qp[1] = W0;
            else if (lane == 7)  qp[2] = W0;
            else if (lane == 15) qp[3] = W0;
            else if (lane == 30) qp[0] = W1F;
            else if (lane == 31) {
                qp[4] = W0; qp[5] = W1; qp[6] = W3;
                qp[7] = W7; qp[8] = WF; qp[9] = W1F;
            }
        }
        __syncthreads();

        // ---- LSTM cell update (lanes 0-9 of every warp, redundant) ----
        if (lane < HH) {
            const int h = lane;
            float qf = S->qpart[par][0][h];
            float qi = S->qpart[par][1][h];
            float qg = S->qpart[par][2][h];
            float qo = S->qpart[par][3][h];
            float fg = fast_sigmoid(qf);
            float ig = fast_sigmoid(qi);
            float gg = fast_tanh(qg);
            float og = fast_sigmoid(qo);
            cx_reg = fg * cx_reg + ig * gg;
            hx_reg = og * fast_tanh(cx_reg);
            if (c == 0)
                out[((size_t)(t*BB) + b)*HH + h] = hx_reg;
        }
        __syncwarp();
    }

    if (c == 0 && lane < HH) {
        out[(size_t)TT*BB*HH + (size_t)b*HH + lane]                 = hx_reg;
        out[(size_t)TT*BB*HH + (size_t)BB*HH + (size_t)b*HH + lane] = cx_reg;
    }
}

extern "C" void kernel_launch(void* const* d_in, const int* in_sizes, int n_in,
                              void* d_out, int out_size) {
    (void)in_sizes; (void)n_in; (void)out_size;
    const float* inputs  = (const float*)d_in[0];
    const float* qparams = (const float*)d_in[1];
    const float* Wf = (const float*)d_in[2];
    const float* bf = (const float*)d_in[3];
    const float* Wi = (const float*)d_in[4];
    const float* bi = (const float*)d_in[5];
    const float* Wg = (const float*)d_in[6];
    const float* bg = (const float*)d_in[7];
    const float* Wo = (const float*)d_in[8];
    const float* bo = (const float*)d_in[9];
    float* out = (float*)d_out;
    cudaFuncSetAttribute(qlstm_kernel,
                         cudaFuncAttributeMaxDynamicSharedMemorySize,
                         (int)sizeof(Smem));
    qlstm_kernel<<<BB, NTH, sizeof(Smem)>>>(inputs, qparams, Wf, bf, Wi, bi,
                                            Wg, bg, Wo, bo, out);
}

// round 11
// speedup vs baseline: 1.8229x; 1.0019x over previous
#include <cuda_runtime.h>

// QLSTM on GB300. One CTA/batch element, warp-per-circuit, 32 amps/thread.
// Split re/im f32x2 packing + phase-normalized L2 gates.
// R9: L2 wires 0,1,2 folded into the 16-entry product table.
// R10: L2 wire 4 folded into the H quad; table as ulonglong2.
// R11: packed-f32x2 Walsh reduction tree (5 packed accumulators, 6 scalar
// extracts) + sign-premultiplied single-lane reductions for the 4 Walsh
// values consumed only at lane 31.

#define TT 64
#define BB 256
#define DD 32
#define HH 10
#define NTH 128

typedef unsigned long long u64;

struct Smem {
    float      svr[4][1024];     // statevector re (also setup scratch)
    float      svi[4][1024];     // statevector im
    ulonglong2 TT2[4][16];       // table packs (Tr, Ti)
    u64        sUc2[HH][6];      // L2 gate consts: A2,U2,nU2,V2,nV2,Um
    float4     sU0[HH];          // layer-1 (ax,ay,bx,by)
    u64        venc[4][HH][2];   // per-wire 2-vectors (enc + L1 rot)
    float      sWx[TT][40];      // 0.5*(W.x + b) for all steps/gates/wires
    float      sWh[4][HH][HH];   // 0.5*W_h
    float      qpart[2][4][HH];
};

__device__ __forceinline__ u64 f2fma(u64 a, u64 b, u64 c) {
    u64 d;
    asm("fma.rn.f32x2 %0, %1, %2, %3;" : "=l"(d) : "l"(a), "l"(b), "l"(c));
    return d;
}
__device__ __forceinline__ u64 f2mul(u64 a, u64 b) {
    u64 d;
    asm("mul.rn.f32x2 %0, %1, %2;" : "=l"(d) : "l"(a), "l"(b));
    return d;
}
__device__ __forceinline__ u64 f2add(u64 a, u64 b) {
    u64 d;
    asm("add.rn.f32x2 %0, %1, %2;" : "=l"(d) : "l"(a), "l"(b));
    return d;
}
__device__ __forceinline__ u64 dswp(u64 a) {
    u64 r;
    asm("{\n\t.reg .b32 l, h;\n\tmov.b64 {l, h}, %1;\n\tmov.b64 %0, {h, l};\n\t}"
        : "=l"(r) : "l"(a));
    return r;
}
__device__ __forceinline__ u64 pk(float lo, float hi) {
    return (u64)__float_as_uint(lo) | ((u64)__float_as_uint(hi) << 32);
}
__device__ __forceinline__ float ulo(u64 v) { return __uint_as_float((unsigned)v); }
__device__ __forceinline__ float uhi(u64 v) { return __uint_as_float((unsigned)(v >> 32)); }

__device__ __forceinline__ float fast_tanh(float x) {
    float r;
    asm("tanh.approx.f32 %0, %1;" : "=f"(r) : "f"(x));
    return r;
}
__device__ __forceinline__ float fast_sigmoid(float x) {
    return fmaf(0.5f, fast_tanh(0.5f * x), 0.5f);
}

// low-4 wires linear map of even j (j=2k): contribution of k bits to (x0..x3)
__host__ __device__ constexpr int XLJ2(int k) {
    return ((k & 1) ? 0x6 : 0) ^ ((k & 2) ? 0xC : 0) ^ ((k & 4) ? 0x8 : 0);
}

// phase-normalized clean su2 on k-index bit B: 12 f2 ops
template<int B>
__device__ __forceinline__ void apply_clean(u64 rr[16], u64 ii[16],
                                            const u64* __restrict__ C) {
    u64 A2 = C[0], U2 = C[1], nU2 = C[2], V2 = C[3], nV2 = C[4];
#pragma unroll
    for (int m = 0; m < 16; ++m) {
        if (m & (1 << B)) continue;
        const int m1 = m | (1 << B);
        u64 r0 = rr[m], i0 = ii[m], r1 = rr[m1], i1 = ii[m1];
        rr[m]  = f2fma(A2, r0, f2fma(nU2, r1, f2mul(nV2, i1)));
        ii[m]  = f2fma(A2, i0, f2fma(V2,  r1, f2mul(nU2, i1)));
        rr[m1] = f2fma(A2, r1, f2fma(U2,  r0, f2mul(nV2, i0)));
        ii[m1] = f2fma(A2, i1, f2fma(V2,  r0, f2mul(U2,  i0)));
    }
}

// phase-normalized pack-internal su2: 8 ops
__device__ __forceinline__ void apply_internal(u64 rr[16], u64 ii[16],
                                               const u64* __restrict__ C) {
    u64 A2 = C[0], V2 = C[3], nV2 = C[4], Um = C[5];
#pragma unroll
    for (int m = 0; m < 16; ++m) {
        u64 sr = dswp(rr[m]), si = dswp(ii[m]);
        u64 nr = f2fma(A2, rr[m], f2fma(Um, sr, f2mul(nV2, si)));
        u64 ni = f2fma(A2, ii[m], f2fma(Um, si, f2mul(V2,  sr)));
        rr[m] = nr; ii[m] = ni;
    }
}

// 5-stage signed Walsh butterfly: W[lane] = sum_l v(l) * (-1)^pop(l & lane)
__device__ __forceinline__ float wht5(float v, int lane) {
#pragma unroll
    for (int i = 0; i < 5; ++i) {
        float t = __shfl_xor_sync(0xffffffffu, v, 1 << i);
        v = (lane & (1 << i)) ? (t - v) : (v + t);
    }
    return v;
}

// plain 5-stage sum reduction (all lanes get the warp sum)
__device__ __forceinline__ float redsum(float v) {
#pragma unroll
    for (int i = 0; i < 5; ++i)
        v += __shfl_xor_sync(0xffffffffu, v, 1 << i);
    return v;
}

__global__ void __launch_bounds__(NTH, 2)
qlstm_kernel(const float* __restrict__ inputs,
             const float* __restrict__ qparams,
             const float* __restrict__ Wf, const float* __restrict__ bf,
             const float* __restrict__ Wi, const float* __restrict__ bi,
             const float* __restrict__ Wg, const float* __restrict__ bg,
             const float* __restrict__ Wo, const float* __restrict__ bo,
             float* __restrict__ out)
{
    extern __shared__ char smem_raw[];
    Smem* S = (Smem*)smem_raw;

    const int tid  = threadIdx.x;
    const int b    = blockIdx.x;
    const int c    = tid >> 5;      // circuit == warp
    const int lane = tid & 31;
    const int q    = lane;
    float* svr = S->svr[c];
    float* svi = S->svi[c];

    const float* Ws[4] = {Wf, Wi, Wg, Wo};
    const float* Bs[4] = {bf, bi, bg, bo};

    // ---- setup: stage x into scratch (svr area), gate consts ----
    float* scratch = &S->svr[0][0];
    for (int i = tid; i < TT * DD; i += NTH)
        scratch[i] = inputs[((size_t)(i / DD) * BB + b) * DD + (i % DD)];

    if (tid < 20) {
        int l = tid / 10, w = tid % 10;
        float tz = qparams[(l*10 + w)*3 + 0];
        float tx = qparams[(l*10 + w)*3 + 1];
        float ty = qparams[(l*10 + w)*3 + 2];
        float c1, s1, c2, s2, c3, s3;
        __sincosf(0.5f*tz, &s1, &c1);
        __sincosf(0.5f*tx, &s2, &c2);
        __sincosf(0.5f*ty, &s3, &c3);
        float aAx =  c2*c1, aAy = -c2*s1;   // RX*RZ
        float bAx = -s2*s1, bAy = -s2*c1;
        float ax = c3*aAx - s3*bAx, ay = c3*aAy - s3*bAy;   // U = RY*RX*RZ
        float bx = s3*aAx + c3*bAx, by = s3*aAy + c3*bAy;
        if (l == 0) {
            S->sU0[w] = make_float4(ax, ay, bx, by);
        } else {
            // row-phase normalization: M = [[A, -u+iv],[u+iv, A]], A=|alpha|
            float n2 = ax*ax + ay*ay;
            float inv = rsqrtf(n2);
            float A = n2 * inv;
            float u = inv * (ax*bx - ay*by);
            float v = inv * (ax*by + ay*bx);
            S->sUc2[w][0] = pk( A,  A);
            S->sUc2[w][1] = pk( u,  u);
            S->sUc2[w][2] = pk(-u, -u);
            S->sUc2[w][3] = pk( v,  v);
            S->sUc2[w][4] = pk(-v, -v);
            S->sUc2[w][5] = pk(-u,  u);
        }
    }
    __syncthreads();

    // ---- setup: precompute 0.5*(W.x + b) for all steps ----
    if (tid < 120) {
        const int trio = tid / 40, pr = tid % 40;
        const int g = pr / 10, h = pr % 10;
        const float* Wrow = Ws[g] + h * 42;
        const float bias = Bs[g][h];
        float wreg[DD];
#pragma unroll
        for (int j = 0; j < DD; ++j) wreg[j] = Wrow[j];
        const int t0 = (trio == 0) ? 0 : (trio == 1) ? 22 : 44;
        const int t1 = (trio == 0) ? 22 : (trio == 1) ? 44 : TT;
        for (int t = t0; t < t1; ++t) {
            const float* xv = scratch + t * DD;
            float a0 = 0.f, a1 = 0.f, a2 = 0.f, a3 = 0.f;
#pragma unroll
            for (int j = 0; j < DD; j += 4) {
                a0 = fmaf(wreg[j],   xv[j],   a0);
                a1 = fmaf(wreg[j+1], xv[j+1], a1);
                a2 = fmaf(wreg[j+2], xv[j+2], a2);
                a3 = fmaf(wreg[j+3], xv[j+3], a3);
            }
            S->sWx[t][pr] = 0.5f * (((a0 + a1) + (a2 + a3)) + bias);
        }
    }
    if (tid < 40) {
        const int g = tid / 10, h = tid % 10;
        const float* Wrow = Ws[g] + h * 42 + DD;
#pragma unroll
        for (int j = 0; j < HH; ++j)
            S->sWh[g][h][j] = 0.5f * Wrow[j];
    }
    float cx_reg = 0.f, hx_reg = 0.f;
    const float sgnlane = (__popc(lane) & 1) ? -1.f : 1.f;  // (-1)^pop(lane)
    const u64 NEG1 = 0xBF800000BF800000ull;                 // (-1,-1) packed
    __syncthreads();

    for (int t = 0; t < TT; ++t) {
        const int par = t & 1;

        // ---- pre-activation (h-part only) -> per-wire vectors (lanes 0-9) ----
        float hj[HH];
#pragma unroll
        for (int j = 0; j < HH; ++j)
            hj[j] = __shfl_sync(0xffffffffu, hx_reg, j);
        if (lane < HH) {
            float acc0 = S->sWx[t][c * 10 + lane], acc1 = 0.f;
            const float* wh = S->sWh[c][lane];
#pragma unroll
            for (int j = 0; j < HH; j += 2) {
                acc0 = fmaf(wh[j],   hj[j],   acc0);
                acc1 = fmaf(wh[j+1], hj[j+1], acc1);
            }
            float cc, ss;
            __sincosf(acc0 + acc1, &ss, &cc);
            float4 U = S->sU0[lane];
            S->venc[c][lane][0] = pk(U.x*cc - U.z*ss, U.y*cc + U.w*ss);
            S->venc[c][lane][1] = pk(U.z*cc + U.x*ss, U.w*cc - U.y*ss);
        }
        __syncwarp();

        // ---- table stage (all 32 lanes compute; lanes 0-15 store) ----
        // base product table + L2 gates on wires 0,1,2 folded in
        {
            const int e = lane & 15;
            // base pack entries t0 = T[e], t1 = T[e^3]
            u64 v2v = S->venc[c][2][(e >> 2) & 1];
            u64 v3v = S->venc[c][3][(e >> 3) & 1];
            float Qr, Qi;
            { float ar=ulo(v2v), ai=uhi(v2v), br=ulo(v3v), bi=uhi(v3v);
              Qr = ar*br - ai*bi; Qi = ar*bi + ai*br; }
            u64 v0a = S->venc[c][0][e & 1];
            u64 v1a = S->venc[c][1][(e >> 1) & 1];
            u64 v0b = S->venc[c][0][(e & 1) ^ 1];
            u64 v1b = S->venc[c][1][((e >> 1) & 1) ^ 1];
            float Ar, Ai, Br, Bi;
            { float ar=ulo(v0a), ai=uhi(v0a), br=ulo(v1a), bi=uhi(v1a);
              Ar = ar*br - ai*bi; Ai = ar*bi + ai*br; }
            { float ar=ulo(v0b), ai=uhi(v0b), br=ulo(v1b), bi=uhi(v1b);
              Br = ar*br - ai*bi; Bi = ar*bi + ai*br; }
            float T0r = Ar*Qr - Ai*Qi, T0i = Ar*Qi + Ai*Qr;   // T[e]
            float T1r = Br*Qr - Bi*Qi, T1i = Br*Qi + Bi*Qr;   // T[e^3]

            // wire-0 fold (pack-local): u0 = A t0 - conj(w) t1 ; u1 = A t1 + w t0
            const float A0 = ulo(S->sUc2[0][0]);
            const float u0 = ulo(S->sUc2[0][1]);
            const float v0 = ulo(S->sUc2[0][3]);
            float u0r = A0*T0r - u0*T1r - v0*T1i;
            float u0i = A0*T0i + v0*T1r - u0*T1i;
            float u1r = A0*T1r + u0*T0r - v0*T0i;
            float u1i = A0*T1i + v0*T0r + u0*T0i;
            u64 Tr = pk(u0r, u1r), Ti = pk(u0i, u1i);

            // wire-1 fold: partner mask 6, side bit y1 = e0^e1
            {
                u64 A2 = S->sUc2[1][0], V2 = S->sUc2[1][3], nV2 = S->sUc2[1][4];
                u64 su = ((e ^ (e >> 1)) & 1) ? S->sUc2[1][1] : S->sUc2[1][2];
                u64 pre = __shfl_xor_sync(0xffffffffu, Tr, 6);
                u64 pim = __shfl_xor_sync(0xffffffffu, Ti, 6);
                u64 nTr = f2fma(A2, Tr, f2fma(su, pre, f2mul(nV2, pim)));
                u64 nTi = f2fma(A2, Ti, f2fma(V2,  pre, f2mul(su,  pim)));
                Tr = nTr; Ti = nTi;
            }
            // wire-2 fold: partner mask 0xC, side bit y2 = e0^e1^e2
            {
                u64 A2 = S->sUc2[2][0], V2 = S->sUc2[2][3], nV2 = S->sUc2[2][4];
                u64 su = ((e ^ (e >> 1) ^ (e >> 2)) & 1) ? S->sUc2[2][1] : S->sUc2[2][2];
                u64 pre = __shfl_xor_sync(0xffffffffu, Tr, 0xC);
                u64 pim = __shfl_xor_sync(0xffffffffu, Ti, 0xC);
                u64 nTr = f2fma(A2, Tr, f2fma(su, pre, f2mul(nV2, pim)));
                u64 nTi = f2fma(A2, Ti, f2fma(V2,  pre, f2mul(su,  pim)));
                Tr = nTr; Ti = nTi;
            }
            if (lane < 16)
                S->TT2[c][e] = make_ulonglong2(Tr, Ti);
        }
        __syncwarp();

        // ---- Fused build (ring^-1 product state, w0-2 in table, w4 in H) ----
        u64 rr[16], ii[16];
        {
            const int q0 = q & 1;
            const int q4c = (q & 16) ? 3 : 0;
            const int x6 = (q ^ (q >> 1)) & 1;
            const int x7 = ((q >> 1) ^ (q >> 2)) & 1;
            const int x8 = ((q >> 2) ^ (q >> 3)) & 1;
            const int x9 = ((q >> 3) ^ (q >> 4)) & 1;
            u64 p6 = S->venc[c][6][x6], p7 = S->venc[c][7][x7];
            u64 p8 = S->venc[c][8][x8], p9 = S->venc[c][9][x9];
            float Pr, Pi;
            { float ar=ulo(p6), ai=uhi(p6), br=ulo(p7), bi=uhi(p7);
              Pr = ar*br - ai*bi; Pi = ar*bi + ai*br; }
            { float br=ulo(p8), bi=uhi(p8);
              float nr = Pr*br - Pi*bi; Pi = Pr*bi + Pi*br; Pr = nr; }
            { float br=ulo(p9), bi=uhi(p9);
              float nr = Pr*br - Pi*bi; Pi = Pr*bi + Pi*br; Pr = nr; }
            u64 v40 = S->venc[c][4][0], v41 = S->venc[c][4][1];
            u64 wa  = S->venc[c][5][q0], wb = S->venc[c][5][q0 ^ 1];
            float PA0r, PA0i, PA1r, PA1i;
            { float br=ulo(v40), bi=uhi(v40);
              PA0r = Pr*br - Pi*bi; PA0i = Pr*bi + Pi*br; }
            { float br=ulo(v41), bi=uhi(v41);
              PA1r = Pr*br - Pi*bi; PA1i = Pr*bi + Pi*br; }
            float war = ulo(wa), wai = uhi(wa);
            float wbr = ulo(wb), wbi = uhi(wb);
            float H00r_ = PA0r*war - PA0i*wai, H00i_ = PA0r*wai + PA0i*war;
            float H10r_ = PA1r*war - PA1i*wai, H10i_ = PA1r*wai + PA1i*war;
            float H01r_ = PA1r*wbr - PA1i*wbi, H01i_ = PA1r*wbi + PA1i*wbr;
            float H11r_ = PA0r*wbr - PA0i*wbi, H11i_ = PA0r*wbi + PA0i*wbr;

            // ---- wire-4 gate folded into H quad (k3 flip: H00<->H01, H10<->H11)
            {
                const float A4 = ulo(S->sUc2[4][0]);
                const float u4 = ulo(S->sUc2[4][1]);
                const float v4 = ulo(S->sUc2[4][3]);
                float n00r = A4*H00r_ - u4*H01r_ - v4*H01i_;
                float n00i = A4*H00i_ + v4*H01r_ - u4*H01i_;
                float n01r = A4*H01r_ + u4*H00r_ - v4*H00i_;
                float n01i = A4*H01i_ + v4*H00r_ + u4*H00i_;
                float n10r = A4*H10r_ - u4*H11r_ - v4*H11i_;
                float n10i = A4*H10i_ + v4*H11r_ - u4*H11i_;
                float n11r = A4*H11r_ + u4*H10r_ - v4*H10i_;
                float n11i = A4*H11i_ + v4*H10r_ + u4*H10i_;
                H00r_ = n00r; H00i_ = n00i; H01r_ = n01r; H01i_ = n01i;
                H10r_ = n10r; H10i_ = n10i; H11r_ = n11r; H11i_ = n11i;
            }

            u64 H00r = pk(H00r_, H00r_), H00i = pk(H00i_, H00i_), H00n = pk(-H00i_, -H00i_);
            u64 H10r = pk(H10r_, H10r_), H10i = pk(H10i_, H10i_), H10n = pk(-H10i_, -H10i_);
            u64 H01r = pk(H01r_, H01r_), H01i = pk(H01i_, H01i_), H01n = pk(-H01i_, -H01i_);
            u64 H11r = pk(H11r_, H11r_), H11i = pk(H11i_, H11i_), H11n = pk(-H11i_, -H11i_);
#pragma unroll
            for (int k = 0; k < 16; ++k) {
                const int m = XLJ2(k & 7);
                ulonglong2 tv = S->TT2[c][m ^ q4c];
                u64 Trv = tv.x, Tiv = tv.y;
                u64 hr, hi_, hn;
                if (k < 4)       { hr = H00r; hi_ = H00i; hn = H00n; }
                else if (k < 8)  { hr = H10r; hi_ = H10i; hn = H10n; }
                else if (k < 12) { hr = H01r; hi_ = H01i; hn = H01n; }
                else             { hr = H11r; hi_ = H11i; hn = H11n; }
                rr[k] = f2fma(hr, Trv, f2mul(hn, Tiv));
                ii[k] = f2fma(hr, Tiv, f2mul(hi_, Trv));
            }
        }
        // wire 3 (register bit 2 of k); wire 4 already folded into H
        apply_clean<2>(rr, ii, S->sUc2[3]);
        // swizzled transpose store (scalar floats)
#pragma unroll
        for (int k = 0; k < 16; ++k) {
            const int j0 = 2*k, j1 = 2*k + 1;
            const int a0f = (j0 << 5) | (q ^ ((j0 << 1) & 30));
            const int a1f = (j1 << 5) | (q ^ ((j1 << 1) & 30));
            svr[a0f] = ulo(rr[k]); svr[a1f] = uhi(rr[k]);
            svi[a0f] = ulo(ii[k]); svi[a1f] = uhi(ii[k]);
        }
        __syncwarp();

        // ---- P5: packed reload, L2 wires 5-9, Walsh expectations ----
#pragma unroll
        for (int k = 0; k < 16; ++k) {
            const int fa = (q << 5) | ((2*k) ^ ((q << 1) & 30));
            rr[k] = *(const u64*)(svr + fa);
            ii[k] = *(const u64*)(svi + fa);
        }
        apply_internal(rr, ii, S->sUc2[5]);      // wire 5 (pack bit)
        apply_clean<0>(rr, ii, S->sUc2[6]);
        apply_clean<1>(rr, ii, S->sUc2[7]);
        apply_clean<2>(rr, ii, S->sUc2[8]);
        apply_clean<3>(rr, ii, S->sUc2[9]);
        {
            // packed probs
            u64 pp[16];
#pragma unroll
            for (int k = 0; k < 16; ++k)
                pp[k] = f2fma(rr[k], rr[k], f2mul(ii[k], ii[k]));

            // packed Walsh tree over k bits; 5 packed accumulators
            u64 s1[8], d1[8];
#pragma unroll
            for (int i = 0; i < 8; ++i) {
                s1[i] = f2add(pp[2*i], pp[2*i+1]);
                d1[i] = f2fma(pp[2*i+1], NEG1, pp[2*i]);
            }
            u64 A0 = f2add(f2add(f2add(s1[0], s1[1]), f2add(s1[2], s1[3])),
                           f2add(f2add(s1[4], s1[5]), f2add(s1[6], s1[7])));
            u64 s2[4], d2[4];
#pragma unroll
            for (int i = 0; i < 4; ++i) {
                s2[i] = f2add(d1[2*i], d1[2*i+1]);
                d2[i] = f2fma(d1[2*i+1], NEG1, d1[2*i]);
            }
            u64 A1 = f2add(f2add(s2[0], s2[1]), f2add(s2[2], s2[3]));
            u64 s3a = f2add(d2[0], d2[1]), s3b = f2add(d2[2], d2[3]);
            u64 d3a = f2fma(d2[1], NEG1, d2[0]);
            u64 d3b = f2fma(d2[3], NEG1, d2[2]);
            u64 A2 = f2add(s3a, s3b);
            u64 A3 = f2add(d3a, d3b);
            u64 A4 = f2fma(d3b, NEG1, d3a);

            float Sh0  = ulo(A0) + uhi(A0);
            float Sh1  = ulo(A0) - uhi(A0);
            float Sh3  = ulo(A1) - uhi(A1);
            float Sh7  = ulo(A2) - uhi(A2);
            float ShF  = ulo(A3) - uhi(A3);
            float Sh1F = ulo(A4) - uhi(A4);

            // W0 needed at lanes {3,7,15,31}: full butterfly.
            // W1F needed at lanes {30,31}: full butterfly.
            // W1,W3,W7,WF needed only at lane 31: wht5(v)[31] = sum sgn*v.
            float W0  = wht5(Sh0,  lane);
            float W1F = wht5(Sh1F, lane);
            float W1  = redsum(Sh1 * sgnlane);
            float W3  = redsum(Sh3 * sgnlane);
            float W7  = redsum(Sh7 * sgnlane);
            float WF  = redsum(ShF * sgnlane);

            float* qp = S->qpart[par][c];
            if      (lane == 3)  qp[1] = W0;
            else if (lane == 7)  qp[2] = W0;
            else if (lane == 15) qp[3] = W0;
            else if (lane == 30) qp[0] = W1F;
            else if (lane == 31) {
                qp[4] = W0; qp[5] = W1; qp[6] = W3;
                qp[7] = W7; qp[8] = WF; qp[9] = W1F;
            }
        }
        __syncthreads();

        // ---- LSTM cell update (lanes 0-9 of every warp, redundant) ----
        if (lane < HH) {
            const int h = lane;
            float qf = S->qpart[par][0][h];
            float qi = S->qpart[par][1][h];
            float qg = S->qpart[par][2][h];
            float qo = S->qpart[par][3][h];
            float fg = fast_sigmoid(qf);
            float ig = fast_sigmoid(qi);
            float gg = fast_tanh(qg);
            float og = fast_sigmoid(qo);
            cx_reg = fg * cx_reg + ig * gg;
            hx_reg = og * fast_tanh(cx_reg);
            if (c == 0)
                out[((size_t)(t*BB) + b)*HH + h] = hx_reg;
        }
        __syncwarp();
    }

    if (c == 0 && lane < HH) {
        out[(size_t)TT*BB*HH + (size_t)b*HH + lane]                 = hx_reg;
        out[(size_t)TT*BB*HH + (size_t)BB*HH + (size_t)b*HH + lane] = cx_reg;
    }
}

extern "C" void kernel_launch(void* const* d_in, const int* in_sizes, int n_in,
                              void* d_out, int out_size) {
    (void)in_sizes; (void)n_in; (void)out_size;
    const float* inputs  = (const float*)d_in[0];
    const float* qparams = (const float*)d_in[1];
    const float* Wf = (const float*)d_in[2];
    const float* bf = (const float*)d_in[3];
    const float* Wi = (const float*)d_in[4];
    const float* bi = (const float*)d_in[5];
    const float* Wg = (const float*)d_in[6];
    const float* bg = (const float*)d_in[7];
    const float* Wo = (const float*)d_in[8];
    const float* bo = (const float*)d_in[9];
    float* out = (float*)d_out;
    cudaFuncSetAttribute(qlstm_kernel,
                         cudaFuncAttributeMaxDynamicSharedMemorySize,
                         (int)sizeof(Smem));
    qlstm_kernel<<<BB, NTH, sizeof(Smem)>>>(inputs, qparams, Wf, bf, Wi, bi,
                                            Wg, bg, Wo, bo, out);
}

// round 13
// speedup vs baseline: 2.5962x; 1.4243x over previous
#include <cuda_runtime.h>

// QLSTM on GB300 — R13: TRANSFER-MATRIX formulation (exact), E0 fixed.
// Per circuit per step:  <Z_w> = <psi| (x)_j M_j |psi>,  psi = Ring1 (x)v_j,
// M_j = N_j = U_j^dag Z U_j for j in prefix-mask(w), else I.
// Ring prefix-linearity => 4x4 complex transfer chain over (p',p):
//   Rm_w = Gm_w ... Gm_1 R0   (masked prefix, lanes 0-15)
//   Su_w = Gu_9 ... Gu_{w+1}  (unmasked suffix, lanes 16-31; Su_9 = I)
//   E_w  = sum K.(Su_w Rm_w)  (K = wire-0 boundary kernel),
//   E_0  = sum over delta_{q',q}: Rm_9[row,row] + Rm_9[row,row^3]  (R13 FIX).
// One warp per circuit; both chains in one warp; no statevector at all.

#define TT 64
#define BB 256
#define DD 32
#define HH 10
#define NTH 128

struct Smem {
    float2 sRm[4][10][16];      // masked prefix snapshots (w=1..9) -- also setup scratch
    float2 sSu[4][10][16];      // unmasked suffix snapshots ([9]=I, [0] dummy)
    float2 sv[4][HH][2];        // per-circuit per-wire vectors (step-dependent)
    float2 sN[HH][4];           // N_j = U_j^dag Z U_j  (fixed)
    float2 sK[16];              // boundary kernel K[r,c] = N0[(a'^p9')*2+(a^p9)]
    float4 sU0[HH];             // layer-1 gate (ax,ay,bx,by)
    float  sWx[TT][40];         // 0.5*(W.x + b) all steps
    float  sWh[4][HH][HH];      // 0.5*W_h
    float  qpart[2][4][HH];
};

__device__ __forceinline__ float2 cmul(float2 a, float2 b) {
    return make_float2(a.x*b.x - a.y*b.y, a.x*b.y + a.y*b.x);
}
__device__ __forceinline__ float2 cmulc(float2 a, float2 b) {   // conj(a)*b
    return make_float2(a.x*b.x + a.y*b.y, a.x*b.y - a.y*b.x);
}
__device__ __forceinline__ float2 cfma(float2 a, float2 b, float2 acc) {
    acc.x = fmaf(a.x, b.x, fmaf(-a.y, b.y, acc.x));
    acc.y = fmaf(a.x, b.y, fmaf( a.y, b.x, acc.y));
    return acc;
}

__device__ __forceinline__ float fast_tanh(float x) {
    float r;
    asm("tanh.approx.f32 %0, %1;" : "=f"(r) : "f"(x));
    return r;
}
__device__ __forceinline__ float fast_sigmoid(float x) {
    return fmaf(0.5f, fast_tanh(0.5f * x), 0.5f);
}

__global__ void __launch_bounds__(NTH, 2)
qlstm_kernel(const float* __restrict__ inputs,
             const float* __restrict__ qparams,
             const float* __restrict__ Wf, const float* __restrict__ bf,
             const float* __restrict__ Wi, const float* __restrict__ bi,
             const float* __restrict__ Wg, const float* __restrict__ bg,
             const float* __restrict__ Wo, const float* __restrict__ bo,
             float* __restrict__ out)
{
    extern __shared__ char smem_raw[];
    Smem* S = (Smem*)smem_raw;

    const int tid  = threadIdx.x;
    const int b    = blockIdx.x;
    const int c    = tid >> 5;        // circuit == warp
    const int lane = tid & 31;
    const int half = lane >> 4;       // 0: Rm chain, 1: Su chain
    const int ln   = lane & 15;
    const int row  = ln >> 2;
    const int col  = ln & 3;

    const float* Ws[4] = {Wf, Wi, Wg, Wo};
    const float* Bs[4] = {bf, bi, bg, bo};

    // ---- setup phase 1: stage x into scratch (sRm/sSu region), gate consts --
    float* scratch = (float*)&S->sRm[0][0][0];
    for (int i = tid; i < TT * DD; i += NTH)
        scratch[i] = inputs[((size_t)(i / DD) * BB + b) * DD + (i % DD)];

    if (tid < 20) {
        int l = tid / 10, w = tid % 10;
        float tz = qparams[(l*10 + w)*3 + 0];
        float tx = qparams[(l*10 + w)*3 + 1];
        float ty = qparams[(l*10 + w)*3 + 2];
        float c1, s1, c2, s2, c3, s3;
        __sincosf(0.5f*tz, &s1, &c1);
        __sincosf(0.5f*tx, &s2, &c2);
        __sincosf(0.5f*ty, &s3, &c3);
        float aAx =  c2*c1, aAy = -c2*s1;   // RX*RZ
        float bAx = -s2*s1, bAy = -s2*c1;
        float ax = c3*aAx - s3*bAx, ay = c3*aAy - s3*bAy;   // U = RY*RX*RZ
        float bx = s3*aAx + c3*bAx, by = s3*aAy + c3*bAy;
        if (l == 0) {
            S->sU0[w] = make_float4(ax, ay, bx, by);
        } else {
            // N = U^dag Z U ; alpha = ax+i ay, beta = bx+i by
            float n00 = ax*ax + ay*ay - bx*bx - by*by;
            float pr  = ax*bx - ay*by;        // Re(alpha*beta)
            float pi_ = ax*by + ay*bx;        // Im(alpha*beta)
            S->sN[w][0] = make_float2( n00, 0.f);
            S->sN[w][1] = make_float2(-2.f*pr,  2.f*pi_);   // -2 conj(a)conj(b)
            S->sN[w][2] = make_float2(-2.f*pr, -2.f*pi_);   // -2 a b
            S->sN[w][3] = make_float2(-n00, 0.f);
        }
    }
    __syncthreads();

    // ---- setup phase 2: precompute 0.5*(W.x + b); W_h; K kernel ----
    if (tid < 120) {
        const int trio = tid / 40, pr = tid % 40;
        const int g = pr / 10, h = pr % 10;
        const float* Wrow = Ws[g] + h * 42;
        const float bias = Bs[g][h];
        float wreg[DD];
#pragma unroll
        for (int j = 0; j < DD; ++j) wreg[j] = Wrow[j];
        const int t0 = (trio == 0) ? 0 : (trio == 1) ? 22 : 44;
        const int t1 = (trio == 0) ? 22 : (trio == 1) ? 44 : TT;
        for (int t = t0; t < t1; ++t) {
            const float* xv = scratch + t * DD;
            float a0 = 0.f, a1 = 0.f, a2 = 0.f, a3 = 0.f;
#pragma unroll
            for (int j = 0; j < DD; j += 4) {
                a0 = fmaf(wreg[j],   xv[j],   a0);
                a1 = fmaf(wreg[j+1], xv[j+1], a1);
                a2 = fmaf(wreg[j+2], xv[j+2], a2);
                a3 = fmaf(wreg[j+3], xv[j+3], a3);
            }
            S->sWx[t][pr] = 0.5f * (((a0 + a1) + (a2 + a3)) + bias);
        }
    }
    if (tid < 40) {
        const int g = tid / 10, h = tid % 10;
        const float* Wrow = Ws[g] + h * 42 + DD;
#pragma unroll
        for (int j = 0; j < HH; ++j)
            S->sWh[g][h][j] = 0.5f * Wrow[j];
    }
    if (tid < 16) {
        int r = tid >> 2, cc = tid & 3;
        int idx = (((cc >> 1) ^ (r >> 1)) << 1) | ((cc & 1) ^ (r & 1));
        S->sK[tid] = S->sN[0][idx];
    }
    __syncthreads();

    // ---- setup phase 3: Su_9 = I (after scratch is consumed) ----
    if (tid < 64) {
        int cc = tid >> 4, e = tid & 15;
        S->sSu[cc][9][e] = make_float2((e >> 2) == (e & 3) ? 1.f : 0.f, 0.f);
    }

    // ---- per-lane chain constants (wire-independent) ----
    int i1k[4], i2k[4], srck[4];
    float cmk[4];
    if (half == 0) {
        const int sp = row >> 1, s = row & 1;
#pragma unroll
        for (int k = 0; k < 4; ++k) {
            i1k[k] = sp ^ (k >> 1);
            i2k[k] = s  ^ (k & 1);
            srck[k] = k * 4 + col;
            cmk[k] = 1.f;
        }
    } else {
        const int tp = col >> 1, t2 = col & 1;
        i1k[0] = tp;     i2k[0] = t2;     srck[0] = 16 + row*4 + 0; cmk[0] = 1.f;
        i1k[1] = 1 ^ tp; i2k[1] = 1 ^ t2; srck[1] = 16 + row*4 + 3; cmk[1] = 1.f;
        i1k[2] = 0; i2k[2] = 0; srck[2] = lane; cmk[2] = 0.f;
        i1k[3] = 0; i2k[3] = 0; srck[3] = lane; cmk[3] = 0.f;
    }

    float cx_reg = 0.f, hx_reg = 0.f;
    __syncthreads();

    for (int t = 0; t < TT; ++t) {
        const int par = t & 1;

        // ---- pre-activation (h-part) -> per-wire vectors (lanes 0-9) ----
        float hj[HH];
#pragma unroll
        for (int j = 0; j < HH; ++j)
            hj[j] = __shfl_sync(0xffffffffu, hx_reg, j);
        if (lane < HH) {
            float acc0 = S->sWx[t][c * 10 + lane], acc1 = 0.f;
            const float* wh = S->sWh[c][lane];
#pragma unroll
            for (int j = 0; j < HH; j += 2) {
                acc0 = fmaf(wh[j],   hj[j],   acc0);
                acc1 = fmaf(wh[j+1], hj[j+1], acc1);
            }
            float cc, ss;
            __sincosf(acc0 + acc1, &ss, &cc);
            float4 U = S->sU0[lane];
            S->sv[c][lane][0] = make_float2(U.x*cc - U.z*ss, U.y*cc + U.w*ss);
            S->sv[c][lane][1] = make_float2(U.z*cc + U.x*ss, U.w*cc - U.y*ss);
        }
        __syncwarp();

        // ---- dual transfer chains: Rm (lanes 0-15), Su (lanes 16-31) ----
        float2 R;
        if (half == 0) {
            if (row == col) {
                float2 v0a = S->sv[c][0][col >> 1];
                float2 v0b = S->sv[c][0][col & 1];
                R = cmulc(v0a, v0b);             // conj(v0[a']) * v0[a]
            } else {
                R = make_float2(0.f, 0.f);
            }
        } else {
            R = make_float2((row == col) ? 1.f : 0.f, 0.f);
        }
#pragma unroll
        for (int i = 0; i < 9; ++i) {
            const int j = half ? (9 - i) : (i + 1);
            float2 va = S->sv[c][j][0];
            float2 vb = S->sv[c][j][1];
            // coefficients conj(v[i1]) * v[i2]
            float2 cf[4];
#pragma unroll
            for (int k = 0; k < 4; ++k) {
                float2 u  = i1k[k] ? vb : va;
                float2 w2 = i2k[k] ? vb : va;
                float2 cc = cmulc(u, w2);
                cf[k] = make_float2(cc.x * cmk[k], cc.y * cmk[k]);
            }
            // gather partner values
            float2 old[4];
#pragma unroll
            for (int k = 0; k < 4; ++k) {
                old[k].x = __shfl_sync(0xffffffffu, R.x, srck[k]);
                old[k].y = __shfl_sync(0xffffffffu, R.y, srck[k]);
            }
            float2 acc = make_float2(0.f, 0.f);
#pragma unroll
            for (int k = 0; k < 4; ++k)
                acc = cfma(cf[k], old[k], acc);
            if (half == 0) {
                float2 Nv = S->sN[j][row];
                R = cmul(Nv, acc);
                S->sRm[c][i + 1][ln] = R;
            } else {
                R = acc;
                S->sSu[c][8 - i][ln] = R;     // i=8 -> dummy slot 0
            }
        }
        __syncwarp();

        // ---- combine: E_w = Re sum K .* (Su_w Rm_w) ----
#pragma unroll
        for (int p = 0; p < 5; ++p) {
            const int w = 1 + 2*p + half;
            float e = 0.f;
            if (w <= 9) {
                float2 Cv = make_float2(0.f, 0.f);
#pragma unroll
                for (int tt = 0; tt < 4; ++tt) {
                    float2 su = S->sSu[c][w][row*4 + tt];
                    float2 rm = S->sRm[c][w][tt*4 + col];
                    Cv = cfma(su, rm, Cv);
                }
                float2 Kv = S->sK[ln];
                e = fmaf(Kv.x, Cv.x, -Kv.y * Cv.y);
            }
            e += __shfl_xor_sync(0xffffffffu, e, 1);
            e += __shfl_xor_sync(0xffffffffu, e, 2);
            e += __shfl_xor_sync(0xffffffffu, e, 4);
            e += __shfl_xor_sync(0xffffffffu, e, 8);
            if (ln == 0 && w <= 9)
                S->qpart[par][c][w] = e;
        }
        // ---- E_0: delta_{q',q} -> col = row (q'^q=0) AND col = row^3 (=1) ----
        if (lane == 0) {
            const float2* Rm9 = S->sRm[c][9];
            float e0 = Rm9[0].x + Rm9[5].x + Rm9[10].x + Rm9[15].x
                     + Rm9[3].x + Rm9[6].x + Rm9[9].x  + Rm9[12].x;
            S->qpart[par][c][0] = e0;
        }
        __syncthreads();

        // ---- LSTM cell update (lanes 0-9 of every warp, redundant) ----
        if (lane < HH) {
            const int h = lane;
            float qf = S->qpart[par][0][h];
            float qi = S->qpart[par][1][h];
            float qg = S->qpart[par][2][h];
            float qo = S->qpart[par][3][h];
            float fg = fast_sigmoid(qf);
            float ig = fast_sigmoid(qi);
            float gg = fast_tanh(qg);
            float og = fast_sigmoid(qo);
            cx_reg = fg * cx_reg + ig * gg;
            hx_reg = og * fast_tanh(cx_reg);
            if (c == 0)
                out[((size_t)(t*BB) + b)*HH + h] = hx_reg;
        }
        __syncwarp();
    }

    if (c == 0 && lane < HH) {
        out[(size_t)TT*BB*HH + (size_t)b*HH + lane]                 = hx_reg;
        out[(size_t)TT*BB*HH + (size_t)BB*HH + (size_t)b*HH + lane] = cx_reg;
    }
}

extern "C" void kernel_launch(void* const* d_in, const int* in_sizes, int n_in,
                              void* d_out, int out_size) {
    (void)in_sizes; (void)n_in; (void)out_size;
    const float* inputs  = (const float*)d_in[0];
    const float* qparams = (const float*)d_in[1];
    const float* Wf = (const float*)d_in[2];
    const float* bf = (const float*)d_in[3];
    const float* Wi = (const float*)d_in[4];
    const float* bi = (const float*)d_in[5];
    const float* Wg = (const float*)d_in[6];
    const float* bg = (const float*)d_in[7];
    const float* Wo = (const float*)d_in[8];
    const float* bo = (const float*)d_in[9];
    float* out = (float*)d_out;
    cudaFuncSetAttribute(qlstm_kernel,
                         cudaFuncAttributeMaxDynamicSharedMemorySize,
                         (int)sizeof(Smem));
    qlstm_kernel<<<BB, NTH, sizeof(Smem)>>>(inputs, qparams, Wf, bf, Wi, bi,
                                            Wg, bg, Wo, bo, out);
}

// round 14
// speedup vs baseline: 2.7256x; 1.0498x over previous
#include <cuda_runtime.h>

// QLSTM on GB300 — R14: transfer-matrix formulation with K-contracted
// suffix chain.
//   Rm_w = Gm_w ... Gm_1 R0          (masked prefix, lanes 0-15)
//   L_w  = K-contracted suffix:  L_9 = K,  L_{w-1}[t,c] = sum_s Gu_w[s,t] L_w[s,c]
//                                     (lanes 16-31)
//   E_w  = Re sum_{t,c} L_w[t,c] Rm_w[t,c]   (elementwise dot, not matmul)
//   E_0  = masked register reduce over final Rm_9 (delta_{q',q} entries).
// One warp per circuit; both chains run concurrently in one unified loop.

#define TT 64
#define BB 256
#define DD 32
#define HH 10
#define NTH 128

struct Smem {
    float2 sRm[4][10][16];      // masked prefix snapshots (w=1..8 used) + setup scratch
    float2 sL[4][10][16];       // K-contracted suffix snapshots ([9]=K)
    float2 sv[4][HH][2];        // per-circuit per-wire vectors (step-dependent)
    float2 sN[HH][4];           // N_j = U_j^dag Z U_j  (fixed)
    float2 sK[16];              // boundary kernel K[r,c] = N0[(r^c bits)]
    float4 sU0[HH];             // layer-1 gate (ax,ay,bx,by)
    float  sWx[TT][40];         // 0.5*(W.x + b) all steps
    float  sWh[4][HH][HH];      // 0.5*W_h
    float  qpart[2][4][HH];
};

__device__ __forceinline__ float2 cmul(float2 a, float2 b) {
    return make_float2(a.x*b.x - a.y*b.y, a.x*b.y + a.y*b.x);
}
__device__ __forceinline__ float2 cmulc(float2 a, float2 b) {   // conj(a)*b
    return make_float2(a.x*b.x + a.y*b.y, a.x*b.y - a.y*b.x);
}
__device__ __forceinline__ float2 cfma(float2 a, float2 b, float2 acc) {
    acc.x = fmaf(a.x, b.x, fmaf(-a.y, b.y, acc.x));
    acc.y = fmaf(a.x, b.y, fmaf( a.y, b.x, acc.y));
    return acc;
}

__device__ __forceinline__ float fast_tanh(float x) {
    float r;
    asm("tanh.approx.f32 %0, %1;" : "=f"(r) : "f"(x));
    return r;
}
__device__ __forceinline__ float fast_sigmoid(float x) {
    return fmaf(0.5f, fast_tanh(0.5f * x), 0.5f);
}

__global__ void __launch_bounds__(NTH, 2)
qlstm_kernel(const float* __restrict__ inputs,
             const float* __restrict__ qparams,
             const float* __restrict__ Wf, const float* __restrict__ bf,
             const float* __restrict__ Wi, const float* __restrict__ bi,
             const float* __restrict__ Wg, const float* __restrict__ bg,
             const float* __restrict__ Wo, const float* __restrict__ bo,
             float* __restrict__ out)
{
    extern __shared__ char smem_raw[];
    Smem* S = (Smem*)smem_raw;

    const int tid  = threadIdx.x;
    const int b    = blockIdx.x;
    const int c    = tid >> 5;        // circuit == warp
    const int lane = tid & 31;
    const int half = lane >> 4;       // 0: Rm chain, 1: L chain
    const int ln   = lane & 15;
    const int row  = ln >> 2;
    const int col  = ln & 3;

    const float* Ws[4] = {Wf, Wi, Wg, Wo};
    const float* Bs[4] = {bf, bi, bg, bo};

    // ---- setup phase 1: stage x into scratch (sRm region), gate consts ----
    float* scratch = (float*)&S->sRm[0][0][0];
    for (int i = tid; i < TT * DD; i += NTH)
        scratch[i] = inputs[((size_t)(i / DD) * BB + b) * DD + (i % DD)];

    if (tid < 20) {
        int l = tid / 10, w = tid % 10;
        float tz = qparams[(l*10 + w)*3 + 0];
        float tx = qparams[(l*10 + w)*3 + 1];
        float ty = qparams[(l*10 + w)*3 + 2];
        float c1, s1, c2, s2, c3, s3;
        __sincosf(0.5f*tz, &s1, &c1);
        __sincosf(0.5f*tx, &s2, &c2);
        __sincosf(0.5f*ty, &s3, &c3);
        float aAx =  c2*c1, aAy = -c2*s1;   // RX*RZ
        float bAx = -s2*s1, bAy = -s2*c1;
        float ax = c3*aAx - s3*bAx, ay = c3*aAy - s3*bAy;   // U = RY*RX*RZ
        float bx = s3*aAx + c3*bAx, by = s3*aAy + c3*bAy;
        if (l == 0) {
            S->sU0[w] = make_float4(ax, ay, bx, by);
        } else {
            // N = U^dag Z U ; alpha = ax+i ay, beta = bx+i by
            float n00 = ax*ax + ay*ay - bx*bx - by*by;
            float pr  = ax*bx - ay*by;        // Re(alpha*beta)
            float pi_ = ax*by + ay*bx;        // Im(alpha*beta)
            S->sN[w][0] = make_float2( n00, 0.f);
            S->sN[w][1] = make_float2(-2.f*pr,  2.f*pi_);   // -2 conj(a)conj(b)
            S->sN[w][2] = make_float2(-2.f*pr, -2.f*pi_);   // -2 a b
            S->sN[w][3] = make_float2(-n00, 0.f);
        }
    }
    __syncthreads();

    // ---- setup phase 2: precompute 0.5*(W.x + b); W_h; K kernel ----
    if (tid < 120) {
        const int trio = tid / 40, pr = tid % 40;
        const int g = pr / 10, h = pr % 10;
        const float* Wrow = Ws[g] + h * 42;
        const float bias = Bs[g][h];
        float wreg[DD];
#pragma unroll
        for (int j = 0; j < DD; ++j) wreg[j] = Wrow[j];
        const int t0 = (trio == 0) ? 0 : (trio == 1) ? 22 : 44;
        const int t1 = (trio == 0) ? 22 : (trio == 1) ? 44 : TT;
        for (int t = t0; t < t1; ++t) {
            const float* xv = scratch + t * DD;
            float a0 = 0.f, a1 = 0.f, a2 = 0.f, a3 = 0.f;
#pragma unroll
            for (int j = 0; j < DD; j += 4) {
                a0 = fmaf(wreg[j],   xv[j],   a0);
                a1 = fmaf(wreg[j+1], xv[j+1], a1);
                a2 = fmaf(wreg[j+2], xv[j+2], a2);
                a3 = fmaf(wreg[j+3], xv[j+3], a3);
            }
            S->sWx[t][pr] = 0.5f * (((a0 + a1) + (a2 + a3)) + bias);
        }
    }
    if (tid < 40) {
        const int g = tid / 10, h = tid % 10;
        const float* Wrow = Ws[g] + h * 42 + DD;
#pragma unroll
        for (int j = 0; j < HH; ++j)
            S->sWh[g][h][j] = 0.5f * Wrow[j];
    }
    if (tid < 16) {
        int r = tid >> 2, cc = tid & 3;
        int idx = (((cc >> 1) ^ (r >> 1)) << 1) | ((cc & 1) ^ (r & 1));
        S->sK[tid] = S->sN[0][idx];
    }
    __syncthreads();

    // ---- setup phase 3: L_9 = K (after scratch consumed) ----
    if (tid < 64) {
        int cc = tid >> 4, e = tid & 15;
        S->sL[cc][9][e] = S->sK[e];
    }

    // ---- per-lane chain constants (wire-independent) ----
    int i1k[4], i2k[4], srck[4];
    float cmk[4];
    if (half == 0) {
        const int sp = row >> 1, s = row & 1;
#pragma unroll
        for (int k = 0; k < 4; ++k) {
            i1k[k] = sp ^ (k >> 1);
            i2k[k] = s  ^ (k & 1);
            srck[k] = k * 4 + col;
            cmk[k] = 1.f;
        }
    } else {
        // L chain: L_new[row,col] = Gu[0,row] L_old[0,col] + Gu[3,row] L_old[3,col]
        const int rp = row >> 1, r2 = row & 1;
        i1k[0] = rp;     i2k[0] = r2;     srck[0] = 16 + col;      cmk[0] = 1.f;
        i1k[1] = 1 ^ rp; i2k[1] = 1 ^ r2; srck[1] = 16 + 12 + col; cmk[1] = 1.f;
        i1k[2] = 0; i2k[2] = 0; srck[2] = lane; cmk[2] = 0.f;
        i1k[3] = 0; i2k[3] = 0; srck[3] = lane; cmk[3] = 0.f;
    }
    const bool e0_mask = (half == 0) && ((col == row) || (col == (row ^ 3)));

    float cx_reg = 0.f, hx_reg = 0.f;
    __syncthreads();

    for (int t = 0; t < TT; ++t) {
        const int par = t & 1;

        // ---- pre-activation (h-part) -> per-wire vectors (lanes 0-9) ----
        float hj[HH];
#pragma unroll
        for (int j = 0; j < HH; ++j)
            hj[j] = __shfl_sync(0xffffffffu, hx_reg, j);
        if (lane < HH) {
            float acc0 = S->sWx[t][c * 10 + lane], acc1 = 0.f;
            const float* wh = S->sWh[c][lane];
#pragma unroll
            for (int j = 0; j < HH; j += 2) {
                acc0 = fmaf(wh[j],   hj[j],   acc0);
                acc1 = fmaf(wh[j+1], hj[j+1], acc1);
            }
            float cc, ss;
            __sincosf(acc0 + acc1, &ss, &cc);
            float4 U = S->sU0[lane];
            S->sv[c][lane][0] = make_float2(U.x*cc - U.z*ss, U.y*cc + U.w*ss);
            S->sv[c][lane][1] = make_float2(U.z*cc + U.x*ss, U.w*cc - U.y*ss);
        }
        __syncwarp();

        // ---- dual chains: Rm forward (lanes 0-15), L backward (lanes 16-31) --
        float2 R;
        if (half == 0) {
            if (row == col) {
                float2 v0a = S->sv[c][0][col >> 1];
                float2 v0b = S->sv[c][0][col & 1];
                R = cmulc(v0a, v0b);             // conj(v0[a']) * v0[a]
            } else {
                R = make_float2(0.f, 0.f);
            }
        } else {
            R = S->sK[ln];                        // L_9 = K
        }
#pragma unroll
        for (int i = 0; i < 9; ++i) {
            const int j = half ? (9 - i) : (i + 1);
            float2 va = S->sv[c][j][0];
            float2 vb = S->sv[c][j][1];
            float2 cf[4];
#pragma unroll
            for (int k = 0; k < 4; ++k) {
                float2 u  = i1k[k] ? vb : va;
                float2 w2 = i2k[k] ? vb : va;
                float2 cc = cmulc(u, w2);
                cf[k] = make_float2(cc.x * cmk[k], cc.y * cmk[k]);
            }
            float2 old[4];
#pragma unroll
            for (int k = 0; k < 4; ++k) {
                old[k].x = __shfl_sync(0xffffffffu, R.x, srck[k]);
                old[k].y = __shfl_sync(0xffffffffu, R.y, srck[k]);
            }
            float2 acc = make_float2(0.f, 0.f);
#pragma unroll
            for (int k = 0; k < 4; ++k)
                acc = cfma(cf[k], old[k], acc);
            if (half == 0) {
                float2 Nv = S->sN[j][row];
                R = cmul(Nv, acc);
                if (i < 8) S->sRm[c][i + 1][ln] = R;   // Rm_9 stays in R
            } else {
                R = acc;
                if (i < 8) S->sL[c][8 - i][ln] = R;    // L_0 unused
            }
        }

        // ---- E_0: masked register reduce over final Rm_9 ----
        {
            float e0 = e0_mask ? R.x : 0.f;
            e0 += __shfl_xor_sync(0xffffffffu, e0, 1);
            e0 += __shfl_xor_sync(0xffffffffu, e0, 2);
            e0 += __shfl_xor_sync(0xffffffffu, e0, 4);
            e0 += __shfl_xor_sync(0xffffffffu, e0, 8);
            e0 += __shfl_xor_sync(0xffffffffu, e0, 16);
            if (lane == 0)
                S->qpart[par][c][0] = e0;
        }
        __syncwarp();

        // ---- combine: E_w = Re sum_ln L_w[ln] * Rm_w[ln] ----
#pragma unroll
        for (int p = 0; p < 5; ++p) {
            const int w = 1 + 2*p + half;
            float e = 0.f;
            if (w <= 9) {
                float2 L  = S->sL[c][w][ln];
                float2 rm = (p == 4) ? R : S->sRm[c][w][ln];  // w=9: live register
                e = fmaf(L.x, rm.x, -L.y * rm.y);
            }
            e += __shfl_xor_sync(0xffffffffu, e, 1);
            e += __shfl_xor_sync(0xffffffffu, e, 2);
            e += __shfl_xor_sync(0xffffffffu, e, 4);
            e += __shfl_xor_sync(0xffffffffu, e, 8);
            if (ln == 0 && w <= 9)
                S->qpart[par][c][w] = e;
        }
        __syncthreads();

        // ---- LSTM cell update (lanes 0-9 of every warp, redundant) ----
        if (lane < HH) {
            const int h = lane;
            float qf = S->qpart[par][0][h];
            float qi = S->qpart[par][1][h];
            float qg = S->qpart[par][2][h];
            float qo = S->qpart[par][3][h];
            float fg = fast_sigmoid(qf);
            float ig = fast_sigmoid(qi);
            float gg = fast_tanh(qg);
            float og = fast_sigmoid(qo);
            cx_reg = fg * cx_reg + ig * gg;
            hx_reg = og * fast_tanh(cx_reg);
            if (c == 0)
                out[((size_t)(t*BB) + b)*HH + h] = hx_reg;
        }
        __syncwarp();
    }

    if (c == 0 && lane < HH) {
        out[(size_t)TT*BB*HH + (size_t)b*HH + lane]                 = hx_reg;
        out[(size_t)TT*BB*HH + (size_t)BB*HH + (size_t)b*HH + lane] = cx_reg;
    }
}

extern "C" void kernel_launch(void* const* d_in, const int* in_sizes, int n_in,
                              void* d_out, int out_size) {
    (void)in_sizes; (void)n_in; (void)out_size;
    const float* inputs  = (const float*)d_in[0];
    const float* qparams = (const float*)d_in[1];
    const float* Wf = (const float*)d_in[2];
    const float* bf = (const float*)d_in[3];
    const float* Wi = (const float*)d_in[4];
    const float* bi = (const float*)d_in[5];
    const float* Wg = (const float*)d_in[6];
    const float* bg = (const float*)d_in[7];
    const float* Wo = (const float*)d_in[8];
    const float* bo = (const float*)d_in[9];
    float* out = (float*)d_out;
    cudaFuncSetAttribute(qlstm_kernel,
                         cudaFuncAttributeMaxDynamicSharedMemorySize,
                         (int)sizeof(Smem));
    qlstm_kernel<<<BB, NTH, sizeof(Smem)>>>(inputs, qparams, Wf, bf, Wi, bi,
                                            Wg, bg, Wo, bo, out);
}